// round 1
// baseline (speedup 1.0000x reference)
#include <cuda_runtime.h>
#include <cuda_bf16.h>
#include <math.h>

#define NN 50000
#define EE 800000
#define EP (EE + NN)   // 850000 edges incl. self loops
#define HEADS 8
#define HID 64
#define INF_ 256
#define OUTF 40
#define LRELU 0.2f

// ---------------- scratch (device globals: allocation-free contract) ----------
__device__ float g_Wc[512 * 512];       // packed weight for layer0/1 GEMM
__device__ float g_Wh[(size_t)NN * 512];     // Wh of current layer
__device__ float g_h1[(size_t)NN * 512];     // layer0 output / layer2 raw out reuse
__device__ float g_h2[(size_t)NN * 512];     // layer1 output
__device__ float g_ssrc[NN * HEADS];
__device__ float g_sdst[NN * HEADS];
__device__ float g_alpha[(size_t)EP * HEADS];
__device__ int   g_counts[NN];
__device__ int   g_offsets[NN + 1];
__device__ int   g_cursor[NN];
__device__ int   g_csr_src[EP];

// ---------------- CSR build ---------------------------------------------------
__global__ void zero_kernel() {
    int i = blockIdx.x * blockDim.x + threadIdx.x;
    for (; i < NN; i += gridDim.x * blockDim.x) { g_counts[i] = 0; g_cursor[i] = 0; }
}

__global__ void hist_kernel(const int* __restrict__ ei) {
    int e = blockIdx.x * blockDim.x + threadIdx.x;
    if (e >= EP) return;
    int dst = (e < EE) ? ei[EE + e] : (e - EE);
    atomicAdd(&g_counts[dst], 1);
}

__global__ void scan_kernel() {
    __shared__ int s[1024];
    int tid = threadIdx.x;
    int carry = 0;
    for (int base = 0; base < NN; base += 1024) {
        int i = base + tid;
        int v = (i < NN) ? g_counts[i] : 0;
        s[tid] = v;
        __syncthreads();
        for (int off = 1; off < 1024; off <<= 1) {
            int t = (tid >= off) ? s[tid - off] : 0;
            __syncthreads();
            s[tid] += t;
            __syncthreads();
        }
        if (i < NN) g_offsets[i] = carry + s[tid] - v;
        carry += s[1023];
        __syncthreads();
    }
    if (tid == 0) g_offsets[NN] = carry;
}

__global__ void fill_kernel(const int* __restrict__ ei) {
    int e = blockIdx.x * blockDim.x + threadIdx.x;
    if (e >= EP) return;
    int src = (e < EE) ? ei[e] : (e - EE);
    int dst = (e < EE) ? ei[EE + e] : (e - EE);
    int pos = g_offsets[dst] + atomicAdd(&g_cursor[dst], 1);
    g_csr_src[pos] = src;
}

// ---------------- weight pack: [H,K,F] -> [K, H*F] ----------------------------
__global__ void pack_kernel(const float* __restrict__ W, float* __restrict__ out,
                            int K, int H, int F) {
    int idx = blockIdx.x * blockDim.x + threadIdx.x;
    int tot = K * H * F;
    if (idx >= tot) return;
    int k = idx / (H * F);
    int c = idx % (H * F);
    int h = c / F, j = c % F;
    out[idx] = W[(size_t)h * K * F + (size_t)k * F + j];
}

// ---------------- GEMM: C[M,Nc] = A[M,K] @ B[K,Nc], row-major ------------------
__global__ __launch_bounds__(256) void gemm_kernel(const float* __restrict__ A,
                                                   const float* __restrict__ B,
                                                   float* __restrict__ C,
                                                   int M, int Nc, int K) {
    __shared__ float As[16][64];
    __shared__ float Bs[16][64];
    int tid = threadIdx.x;
    int bm = blockIdx.y * 64, bn = blockIdx.x * 64;
    float acc[4][4];
#pragma unroll
    for (int i = 0; i < 4; i++)
#pragma unroll
        for (int j = 0; j < 4; j++) acc[i][j] = 0.f;

    int ar = tid >> 2, ac = (tid & 3) * 4;     // A tile: 64 rows x 16 k
    int br = tid >> 4, bc = (tid & 15) * 4;    // B tile: 16 k x 64 n
    int ty = tid >> 4, tx = tid & 15;

    for (int k0 = 0; k0 < K; k0 += 16) {
        float4 av = make_float4(0.f, 0.f, 0.f, 0.f);
        if (bm + ar < M)
            av = *(const float4*)(A + (size_t)(bm + ar) * K + k0 + ac);
        As[ac + 0][ar] = av.x; As[ac + 1][ar] = av.y;
        As[ac + 2][ar] = av.z; As[ac + 3][ar] = av.w;

        float4 bv = make_float4(0.f, 0.f, 0.f, 0.f);
        if (bn + bc + 3 < Nc)
            bv = *(const float4*)(B + (size_t)(k0 + br) * Nc + bn + bc);
        Bs[br][bc + 0] = bv.x; Bs[br][bc + 1] = bv.y;
        Bs[br][bc + 2] = bv.z; Bs[br][bc + 3] = bv.w;
        __syncthreads();

#pragma unroll
        for (int k = 0; k < 16; k++) {
            float a4[4], b4[4];
#pragma unroll
            for (int i = 0; i < 4; i++) a4[i] = As[k][ty * 4 + i];
#pragma unroll
            for (int j = 0; j < 4; j++) b4[j] = Bs[k][tx * 4 + j];
#pragma unroll
            for (int i = 0; i < 4; i++)
#pragma unroll
                for (int j = 0; j < 4; j++) acc[i][j] += a4[i] * b4[j];
        }
        __syncthreads();
    }
#pragma unroll
    for (int i = 0; i < 4; i++) {
        int r = bm + ty * 4 + i;
        if (r >= M) continue;
#pragma unroll
        for (int j = 0; j < 4; j++) {
            int c = bn + tx * 4 + j;
            if (c < Nc) C[(size_t)r * Nc + c] = acc[i][j];
        }
    }
}

// ---------------- per-node attention scores -----------------------------------
__global__ void scores_kernel(const float* __restrict__ Wh, const float* __restrict__ a,
                              float* __restrict__ ssrc, float* __restrict__ sdst,
                              int H, int F) {
    int idx = blockIdx.x * blockDim.x + threadIdx.x;
    if (idx >= NN * H) return;
    int n = idx / H, h = idx % H;
    const float* w = Wh + (size_t)n * (H * F) + h * F;
    const float* av = a + h * 2 * F;
    float ss = 0.f, sd = 0.f;
    for (int j = 0; j < F; j++) {
        float x = w[j];
        ss += x * av[j];
        sd += x * av[F + j];
    }
    ssrc[idx] = ss;
    sdst[idx] = sd;
}

// ---------------- segment softmax (warp per destination) ----------------------
__global__ void alpha_kernel(const float* __restrict__ ssrc, const float* __restrict__ sdst,
                             float* __restrict__ alpha, int H) {
    int w = (blockIdx.x * blockDim.x + threadIdx.x) >> 5;
    int lane = threadIdx.x & 31;
    if (w >= NN) return;
    int beg = g_offsets[w], end = g_offsets[w + 1];
    for (int h = 0; h < H; h++) {
        float sdh = sdst[w * H + h];
        float m = -1e30f;
        for (int p = beg + lane; p < end; p += 32) {
            float v = ssrc[g_csr_src[p] * H + h] + sdh;
            v = v > 0.f ? v : LRELU * v;
            m = fmaxf(m, v);
        }
#pragma unroll
        for (int o = 16; o; o >>= 1) m = fmaxf(m, __shfl_xor_sync(0xffffffffu, m, o));
        float s = 0.f;
        for (int p = beg + lane; p < end; p += 32) {
            float v = ssrc[g_csr_src[p] * H + h] + sdh;
            v = v > 0.f ? v : LRELU * v;
            float ex = __expf(v - m);
            alpha[(size_t)p * H + h] = ex;
            s += ex;
        }
#pragma unroll
        for (int o = 16; o; o >>= 1) s += __shfl_xor_sync(0xffffffffu, s, o);
        float inv = 1.0f / s;
        for (int p = beg + lane; p < end; p += 32) alpha[(size_t)p * H + h] *= inv;
    }
}

// ---------------- aggregation (block per destination) -------------------------
__global__ void aggregate_kernel(const float* __restrict__ Wh, const float* __restrict__ alpha,
                                 float* __restrict__ out, int H, int Ftot, int apply_elu) {
    int d = blockIdx.x;
    int f = threadIdx.x;
    int beg = g_offsets[d], end = g_offsets[d + 1];
    int Fh = Ftot / H;
    int h = f / Fh;
    if (h >= H) h = 0;
    float acc = 0.f;
    for (int p = beg; p < end; p++) {
        int src = g_csr_src[p];
        float a = alpha[(size_t)p * H + h];
        if (f < Ftot) acc += a * Wh[(size_t)src * Ftot + f];
    }
    if (f < Ftot) {
        float v = acc;
        if (apply_elu) v = v > 0.f ? v : expm1f(v);
        out[(size_t)d * Ftot + f] = v;
    }
}

// ---------------- final elu + log_softmax over 40 classes ---------------------
__global__ void final_kernel(const float* __restrict__ raw, float* __restrict__ out) {
    int w = (blockIdx.x * blockDim.x + threadIdx.x) >> 5;
    int lane = threadIdx.x & 31;
    if (w >= NN) return;
    int j0 = lane, j1 = lane + 32;
    float v0 = -1e30f, v1 = -1e30f;
    if (j0 < OUTF) {
        float x = raw[(size_t)w * OUTF + j0];
        v0 = x > 0.f ? x : expm1f(x);
    }
    if (j1 < OUTF) {
        float x = raw[(size_t)w * OUTF + j1];
        v1 = x > 0.f ? x : expm1f(x);
    }
    float m = fmaxf(v0, v1);
#pragma unroll
    for (int o = 16; o; o >>= 1) m = fmaxf(m, __shfl_xor_sync(0xffffffffu, m, o));
    float s = 0.f;
    if (j0 < OUTF) s += __expf(v0 - m);
    if (j1 < OUTF) s += __expf(v1 - m);
#pragma unroll
    for (int o = 16; o; o >>= 1) s += __shfl_xor_sync(0xffffffffu, s, o);
    float l = logf(s) + m;
    if (j0 < OUTF) out[(size_t)w * OUTF + j0] = v0 - l;
    if (j1 < OUTF) out[(size_t)w * OUTF + j1] = v1 - l;
}

// ---------------- host orchestration ------------------------------------------
extern "C" void kernel_launch(void* const* d_in, const int* in_sizes, int n_in,
                              void* d_out, int out_size) {
    const float* x    = (const float*)d_in[0];
    const int*   ei   = (const int*)d_in[1];
    const float* W0   = (const float*)d_in[2];
    const float* a0   = (const float*)d_in[3];
    const float* W1   = (const float*)d_in[4];
    const float* a1   = (const float*)d_in[5];
    const float* Wout = (const float*)d_in[6];
    const float* aout = (const float*)d_in[7];
    float* out = (float*)d_out;

    float *Wc, *Wh, *h1, *h2, *ssrc, *sdst, *alpha;
    cudaGetSymbolAddress((void**)&Wc, g_Wc);
    cudaGetSymbolAddress((void**)&Wh, g_Wh);
    cudaGetSymbolAddress((void**)&h1, g_h1);
    cudaGetSymbolAddress((void**)&h2, g_h2);
    cudaGetSymbolAddress((void**)&ssrc, g_ssrc);
    cudaGetSymbolAddress((void**)&sdst, g_sdst);
    cudaGetSymbolAddress((void**)&alpha, g_alpha);

    const int TB = 256;
    dim3 gemm_grid_wide(8, (NN + 63) / 64);
    dim3 gemm_grid_out(1, (NN + 63) / 64);

    // CSR build
    zero_kernel<<<(NN + TB - 1) / TB, TB>>>();
    hist_kernel<<<(EP + TB - 1) / TB, TB>>>(ei);
    scan_kernel<<<1, 1024>>>();
    fill_kernel<<<(EP + TB - 1) / TB, TB>>>(ei);

    // ---- layer 0 ----
    pack_kernel<<<(256 * 512 + TB - 1) / TB, TB>>>(W0, Wc, INF_, HEADS, HID);
    gemm_kernel<<<gemm_grid_wide, 256>>>(x, Wc, Wh, NN, 512, INF_);
    scores_kernel<<<(NN * HEADS + TB - 1) / TB, TB>>>(Wh, a0, ssrc, sdst, HEADS, HID);
    alpha_kernel<<<(NN + 7) / 8, 256>>>(ssrc, sdst, alpha, HEADS);
    aggregate_kernel<<<NN, 512>>>(Wh, alpha, h1, HEADS, 512, 1);

    // ---- layer 1 ----
    pack_kernel<<<(512 * 512 + TB - 1) / TB, TB>>>(W1, Wc, 512, HEADS, HID);
    gemm_kernel<<<gemm_grid_wide, 256>>>(h1, Wc, Wh, NN, 512, 512);
    scores_kernel<<<(NN * HEADS + TB - 1) / TB, TB>>>(Wh, a1, ssrc, sdst, HEADS, HID);
    alpha_kernel<<<(NN + 7) / 8, 256>>>(ssrc, sdst, alpha, HEADS);
    aggregate_kernel<<<NN, 512>>>(Wh, alpha, h2, HEADS, 512, 1);

    // ---- layer 2 (single head, F=40) ----
    gemm_kernel<<<gemm_grid_out, 256>>>(h2, Wout, Wh, NN, OUTF, 512);
    scores_kernel<<<(NN + TB - 1) / TB, TB>>>(Wh, aout, ssrc, sdst, 1, OUTF);
    alpha_kernel<<<(NN + 7) / 8, 256>>>(ssrc, sdst, alpha, 1);
    aggregate_kernel<<<NN, 64>>>(Wh, alpha, h1, 1, OUTF, 0);

    // ---- elu + log_softmax ----
    final_kernel<<<(NN + 7) / 8, 256>>>(h1, out);
}

// round 2
// speedup vs baseline: 1.3420x; 1.3420x over previous
#include <cuda_runtime.h>
#include <cuda_bf16.h>
#include <math.h>

#define NN 50000
#define EE 800000
#define EP (EE + NN)   // 850000 edges incl. self loops
#define HEADS 8
#define HID 64
#define INF_ 256
#define OUTF 40
#define LRELU 0.2f

// ---------------- scratch (device globals: allocation-free contract) ----------
__device__ float g_Wc[512 * 512];            // packed weight for layer0/1 GEMM
__device__ float g_Wh[(size_t)NN * 512];     // Wh of current layer
__device__ float g_h1[(size_t)NN * 512];     // layer0 output / layer2 raw out reuse
__device__ float g_h2[(size_t)NN * 512];     // layer1 output
__device__ float g_ssrc[NN * HEADS];
__device__ float g_sdst[NN * HEADS];
__device__ float g_alpha[(size_t)EP * HEADS];
__device__ int   g_counts[NN];
__device__ int   g_offsets[NN + 1];
__device__ int   g_cursor[NN];
__device__ int   g_csr_src[EP];

// ---------------- CSR build ---------------------------------------------------
__global__ void zero_kernel() {
    int i = blockIdx.x * blockDim.x + threadIdx.x;
    for (; i < NN; i += gridDim.x * blockDim.x) { g_counts[i] = 0; g_cursor[i] = 0; }
}

__global__ void hist_kernel(const int* __restrict__ ei) {
    int e = blockIdx.x * blockDim.x + threadIdx.x;
    if (e >= EP) return;
    int dst = (e < EE) ? ei[EE + e] : (e - EE);
    atomicAdd(&g_counts[dst], 1);
}

__global__ void scan_kernel() {
    __shared__ int s[1024];
    int tid = threadIdx.x;
    int carry = 0;
    for (int base = 0; base < NN; base += 1024) {
        int i = base + tid;
        int v = (i < NN) ? g_counts[i] : 0;
        s[tid] = v;
        __syncthreads();
        for (int off = 1; off < 1024; off <<= 1) {
            int t = (tid >= off) ? s[tid - off] : 0;
            __syncthreads();
            s[tid] += t;
            __syncthreads();
        }
        if (i < NN) g_offsets[i] = carry + s[tid] - v;
        carry += s[1023];
        __syncthreads();
    }
    if (tid == 0) g_offsets[NN] = carry;
}

__global__ void fill_kernel(const int* __restrict__ ei) {
    int e = blockIdx.x * blockDim.x + threadIdx.x;
    if (e >= EP) return;
    int src = (e < EE) ? ei[e] : (e - EE);
    int dst = (e < EE) ? ei[EE + e] : (e - EE);
    int pos = g_offsets[dst] + atomicAdd(&g_cursor[dst], 1);
    g_csr_src[pos] = src;
}

// ---------------- weight pack: [H,K,F] -> [K, H*F] ----------------------------
__global__ void pack_kernel(const float* __restrict__ W, float* __restrict__ out,
                            int K, int H, int F) {
    int idx = blockIdx.x * blockDim.x + threadIdx.x;
    int tot = K * H * F;
    if (idx >= tot) return;
    int k = idx / (H * F);
    int c = idx % (H * F);
    int h = c / F, j = c % F;
    out[idx] = W[(size_t)h * K * F + (size_t)k * F + j];
}

// ---------------- tf32 helpers ------------------------------------------------
__device__ __forceinline__ unsigned f2tf(float x) {
    unsigned r;
    asm("cvt.rna.tf32.f32 %0, %1;" : "=r"(r) : "f"(x));
    return r;
}

// ---------------- TF32 tensor-core GEMM: C[M,512] = A[M,K] @ B[K,512] ---------
// BM=128 BN=128 BK=16, 256 threads = 8 warps (4m x 2n), warp tile 32x64.
#define APAD 20   // As row stride (floats) -> conflict-free frag loads
#define BPAD 136  // Bs row stride (floats) -> conflict-free frag loads
__global__ __launch_bounds__(256) void gemm_tf32_kernel(const float* __restrict__ A,
                                                        const float* __restrict__ B,
                                                        float* __restrict__ C,
                                                        int M, int Nc, int K) {
    __shared__ unsigned As[128 * APAD];
    __shared__ unsigned Bs[16 * BPAD];
    int tid = threadIdx.x;
    int wid = tid >> 5, lane = tid & 31;
    int ly = lane >> 2, lx = lane & 3;
    int wm = wid >> 1, wn = wid & 1;     // warp grid 4 x 2
    int bm = blockIdx.y * 128, bn = blockIdx.x * 128;

    float c[2][8][4];
#pragma unroll
    for (int i = 0; i < 2; i++)
#pragma unroll
        for (int j = 0; j < 8; j++)
#pragma unroll
            for (int q = 0; q < 4; q++) c[i][j][q] = 0.f;

    // loader mapping
    int am = tid >> 1;            // 0..127
    int akq = (tid & 1) * 8;      // 0 or 8
    int bk = tid >> 4;            // 0..15
    int bn4 = (tid & 15) * 4;     // 0..60

    for (int k0 = 0; k0 < K; k0 += 16) {
        // A tile: 128 x 16
        float4 a0 = make_float4(0.f, 0.f, 0.f, 0.f), a1 = a0;
        if (bm + am < M) {
            const float* ap = A + (size_t)(bm + am) * K + k0 + akq;
            a0 = *(const float4*)ap;
            a1 = *(const float4*)(ap + 4);
        }
        unsigned* asp = As + am * APAD + akq;
        asp[0] = f2tf(a0.x); asp[1] = f2tf(a0.y); asp[2] = f2tf(a0.z); asp[3] = f2tf(a0.w);
        asp[4] = f2tf(a1.x); asp[5] = f2tf(a1.y); asp[6] = f2tf(a1.z); asp[7] = f2tf(a1.w);

        // B tile: 16 x 128
        const float* bp = B + (size_t)(k0 + bk) * Nc + bn + bn4;
        float4 b0 = *(const float4*)bp;
        float4 b1 = *(const float4*)(bp + 64);
        unsigned* bsp = Bs + bk * BPAD + bn4;
        bsp[0] = f2tf(b0.x); bsp[1] = f2tf(b0.y); bsp[2] = f2tf(b0.z); bsp[3] = f2tf(b0.w);
        bsp[64] = f2tf(b1.x); bsp[65] = f2tf(b1.y); bsp[66] = f2tf(b1.z); bsp[67] = f2tf(b1.w);
        __syncthreads();

#pragma unroll
        for (int kk = 0; kk < 16; kk += 8) {
            unsigned af[2][4];
#pragma unroll
            for (int mt = 0; mt < 2; mt++) {
                int mrow = wm * 32 + mt * 16 + ly;
                af[mt][0] = As[(mrow) * APAD + kk + lx];
                af[mt][1] = As[(mrow + 8) * APAD + kk + lx];
                af[mt][2] = As[(mrow) * APAD + kk + lx + 4];
                af[mt][3] = As[(mrow + 8) * APAD + kk + lx + 4];
            }
            unsigned bf[8][2];
#pragma unroll
            for (int nt = 0; nt < 8; nt++) {
                int ncol = wn * 64 + nt * 8 + ly;
                bf[nt][0] = Bs[(kk + lx) * BPAD + ncol];
                bf[nt][1] = Bs[(kk + lx + 4) * BPAD + ncol];
            }
#pragma unroll
            for (int mt = 0; mt < 2; mt++)
#pragma unroll
                for (int nt = 0; nt < 8; nt++) {
                    asm volatile(
                        "mma.sync.aligned.m16n8k8.row.col.f32.tf32.tf32.f32 "
                        "{%0,%1,%2,%3}, {%4,%5,%6,%7}, {%8,%9}, {%0,%1,%2,%3};\n"
                        : "+f"(c[mt][nt][0]), "+f"(c[mt][nt][1]),
                          "+f"(c[mt][nt][2]), "+f"(c[mt][nt][3])
                        : "r"(af[mt][0]), "r"(af[mt][1]), "r"(af[mt][2]), "r"(af[mt][3]),
                          "r"(bf[nt][0]), "r"(bf[nt][1]));
                }
        }
        __syncthreads();
    }

    // epilogue
#pragma unroll
    for (int mt = 0; mt < 2; mt++) {
#pragma unroll
        for (int nt = 0; nt < 8; nt++) {
            int r0 = bm + wm * 32 + mt * 16 + ly;
            int col = bn + wn * 64 + nt * 8 + 2 * lx;
            if (r0 < M)
                *(float2*)(C + (size_t)r0 * Nc + col) = make_float2(c[mt][nt][0], c[mt][nt][1]);
            int r1 = r0 + 8;
            if (r1 < M)
                *(float2*)(C + (size_t)r1 * Nc + col) = make_float2(c[mt][nt][2], c[mt][nt][3]);
        }
    }
}

// ---------------- fp32 SIMT GEMM (layer 2 only, Nc=40) ------------------------
__global__ __launch_bounds__(256) void gemm_kernel(const float* __restrict__ A,
                                                   const float* __restrict__ B,
                                                   float* __restrict__ C,
                                                   int M, int Nc, int K) {
    __shared__ float As[16][64];
    __shared__ float Bs[16][64];
    int tid = threadIdx.x;
    int bm = blockIdx.y * 64, bn = blockIdx.x * 64;
    float acc[4][4];
#pragma unroll
    for (int i = 0; i < 4; i++)
#pragma unroll
        for (int j = 0; j < 4; j++) acc[i][j] = 0.f;

    int ar = tid >> 2, ac = (tid & 3) * 4;
    int br = tid >> 4, bc = (tid & 15) * 4;
    int ty = tid >> 4, tx = tid & 15;

    for (int k0 = 0; k0 < K; k0 += 16) {
        float4 av = make_float4(0.f, 0.f, 0.f, 0.f);
        if (bm + ar < M)
            av = *(const float4*)(A + (size_t)(bm + ar) * K + k0 + ac);
        As[ac + 0][ar] = av.x; As[ac + 1][ar] = av.y;
        As[ac + 2][ar] = av.z; As[ac + 3][ar] = av.w;

        float4 bv = make_float4(0.f, 0.f, 0.f, 0.f);
        if (bn + bc + 3 < Nc)
            bv = *(const float4*)(B + (size_t)(k0 + br) * Nc + bn + bc);
        Bs[br][bc + 0] = bv.x; Bs[br][bc + 1] = bv.y;
        Bs[br][bc + 2] = bv.z; Bs[br][bc + 3] = bv.w;
        __syncthreads();

#pragma unroll
        for (int k = 0; k < 16; k++) {
            float a4[4], b4[4];
#pragma unroll
            for (int i = 0; i < 4; i++) a4[i] = As[k][ty * 4 + i];
#pragma unroll
            for (int j = 0; j < 4; j++) b4[j] = Bs[k][tx * 4 + j];
#pragma unroll
            for (int i = 0; i < 4; i++)
#pragma unroll
                for (int j = 0; j < 4; j++) acc[i][j] += a4[i] * b4[j];
        }
        __syncthreads();
    }
#pragma unroll
    for (int i = 0; i < 4; i++) {
        int r = bm + ty * 4 + i;
        if (r >= M) continue;
#pragma unroll
        for (int j = 0; j < 4; j++) {
            int c = bn + tx * 4 + j;
            if (c < Nc) C[(size_t)r * Nc + c] = acc[i][j];
        }
    }
}

// ---------------- per-node attention scores -----------------------------------
__global__ void scores_kernel(const float* __restrict__ Wh, const float* __restrict__ a,
                              float* __restrict__ ssrc, float* __restrict__ sdst,
                              int H, int F) {
    int idx = blockIdx.x * blockDim.x + threadIdx.x;
    if (idx >= NN * H) return;
    int n = idx / H, h = idx % H;
    const float* w = Wh + (size_t)n * (H * F) + h * F;
    const float* av = a + h * 2 * F;
    float ss = 0.f, sd = 0.f;
    for (int j = 0; j < F; j++) {
        float x = w[j];
        ss += x * av[j];
        sd += x * av[F + j];
    }
    ssrc[idx] = ss;
    sdst[idx] = sd;
}

// ---------------- segment softmax (warp per destination) ----------------------
__global__ void alpha_kernel(const float* __restrict__ ssrc, const float* __restrict__ sdst,
                             float* __restrict__ alpha, int H) {
    int w = (blockIdx.x * blockDim.x + threadIdx.x) >> 5;
    int lane = threadIdx.x & 31;
    if (w >= NN) return;
    int beg = g_offsets[w], end = g_offsets[w + 1];
    for (int h = 0; h < H; h++) {
        float sdh = sdst[w * H + h];
        float m = -1e30f;
        for (int p = beg + lane; p < end; p += 32) {
            float v = ssrc[g_csr_src[p] * H + h] + sdh;
            v = v > 0.f ? v : LRELU * v;
            m = fmaxf(m, v);
        }
#pragma unroll
        for (int o = 16; o; o >>= 1) m = fmaxf(m, __shfl_xor_sync(0xffffffffu, m, o));
        float s = 0.f;
        for (int p = beg + lane; p < end; p += 32) {
            float v = ssrc[g_csr_src[p] * H + h] + sdh;
            v = v > 0.f ? v : LRELU * v;
            float ex = __expf(v - m);
            alpha[(size_t)p * H + h] = ex;
            s += ex;
        }
#pragma unroll
        for (int o = 16; o; o >>= 1) s += __shfl_xor_sync(0xffffffffu, s, o);
        float inv = 1.0f / s;
        for (int p = beg + lane; p < end; p += 32) alpha[(size_t)p * H + h] *= inv;
    }
}

// ---------------- aggregation (block per destination) -------------------------
__global__ void aggregate_kernel(const float* __restrict__ Wh, const float* __restrict__ alpha,
                                 float* __restrict__ out, int H, int Ftot, int apply_elu) {
    int d = blockIdx.x;
    int f = threadIdx.x;
    int beg = g_offsets[d], end = g_offsets[d + 1];
    int Fh = Ftot / H;
    int h = f / Fh;
    if (h >= H) h = 0;
    float acc = 0.f;
    for (int p = beg; p < end; p++) {
        int src = g_csr_src[p];
        float a = alpha[(size_t)p * H + h];
        if (f < Ftot) acc += a * Wh[(size_t)src * Ftot + f];
    }
    if (f < Ftot) {
        float v = acc;
        if (apply_elu) v = v > 0.f ? v : expm1f(v);
        out[(size_t)d * Ftot + f] = v;
    }
}

// ---------------- final elu + log_softmax over 40 classes ---------------------
__global__ void final_kernel(const float* __restrict__ raw, float* __restrict__ out) {
    int w = (blockIdx.x * blockDim.x + threadIdx.x) >> 5;
    int lane = threadIdx.x & 31;
    if (w >= NN) return;
    int j0 = lane, j1 = lane + 32;
    float v0 = -1e30f, v1 = -1e30f;
    if (j0 < OUTF) {
        float x = raw[(size_t)w * OUTF + j0];
        v0 = x > 0.f ? x : expm1f(x);
    }
    if (j1 < OUTF) {
        float x = raw[(size_t)w * OUTF + j1];
        v1 = x > 0.f ? x : expm1f(x);
    }
    float m = fmaxf(v0, v1);
#pragma unroll
    for (int o = 16; o; o >>= 1) m = fmaxf(m, __shfl_xor_sync(0xffffffffu, m, o));
    float s = 0.f;
    if (j0 < OUTF) s += __expf(v0 - m);
    if (j1 < OUTF) s += __expf(v1 - m);
#pragma unroll
    for (int o = 16; o; o >>= 1) s += __shfl_xor_sync(0xffffffffu, s, o);
    float l = logf(s) + m;
    if (j0 < OUTF) out[(size_t)w * OUTF + j0] = v0 - l;
    if (j1 < OUTF) out[(size_t)w * OUTF + j1] = v1 - l;
}

// ---------------- host orchestration ------------------------------------------
extern "C" void kernel_launch(void* const* d_in, const int* in_sizes, int n_in,
                              void* d_out, int out_size) {
    const float* x    = (const float*)d_in[0];
    const int*   ei   = (const int*)d_in[1];
    const float* W0   = (const float*)d_in[2];
    const float* a0   = (const float*)d_in[3];
    const float* W1   = (const float*)d_in[4];
    const float* a1   = (const float*)d_in[5];
    const float* Wout = (const float*)d_in[6];
    const float* aout = (const float*)d_in[7];
    float* out = (float*)d_out;

    float *Wc, *Wh, *h1, *h2, *ssrc, *sdst, *alpha;
    cudaGetSymbolAddress((void**)&Wc, g_Wc);
    cudaGetSymbolAddress((void**)&Wh, g_Wh);
    cudaGetSymbolAddress((void**)&h1, g_h1);
    cudaGetSymbolAddress((void**)&h2, g_h2);
    cudaGetSymbolAddress((void**)&ssrc, g_ssrc);
    cudaGetSymbolAddress((void**)&sdst, g_sdst);
    cudaGetSymbolAddress((void**)&alpha, g_alpha);

    const int TB = 256;
    dim3 tf32_grid(4, (NN + 127) / 128);     // Nc=512 tiles of 128
    dim3 gemm_grid_out(1, (NN + 63) / 64);

    // CSR build
    zero_kernel<<<(NN + TB - 1) / TB, TB>>>();
    hist_kernel<<<(EP + TB - 1) / TB, TB>>>(ei);
    scan_kernel<<<1, 1024>>>();
    fill_kernel<<<(EP + TB - 1) / TB, TB>>>(ei);

    // ---- layer 0 ----
    pack_kernel<<<(256 * 512 + TB - 1) / TB, TB>>>(W0, Wc, INF_, HEADS, HID);
    gemm_tf32_kernel<<<tf32_grid, 256>>>(x, Wc, Wh, NN, 512, INF_);
    scores_kernel<<<(NN * HEADS + TB - 1) / TB, TB>>>(Wh, a0, ssrc, sdst, HEADS, HID);
    alpha_kernel<<<(NN + 7) / 8, 256>>>(ssrc, sdst, alpha, HEADS);
    aggregate_kernel<<<NN, 512>>>(Wh, alpha, h1, HEADS, 512, 1);

    // ---- layer 1 ----
    pack_kernel<<<(512 * 512 + TB - 1) / TB, TB>>>(W1, Wc, 512, HEADS, HID);
    gemm_tf32_kernel<<<tf32_grid, 256>>>(h1, Wc, Wh, NN, 512, 512);
    scores_kernel<<<(NN * HEADS + TB - 1) / TB, TB>>>(Wh, a1, ssrc, sdst, HEADS, HID);
    alpha_kernel<<<(NN + 7) / 8, 256>>>(ssrc, sdst, alpha, HEADS);
    aggregate_kernel<<<NN, 512>>>(Wh, alpha, h2, HEADS, 512, 1);

    // ---- layer 2 (single head, F=40, exact fp32) ----
    gemm_kernel<<<gemm_grid_out, 256>>>(h2, Wout, Wh, NN, OUTF, 512);
    scores_kernel<<<(NN + TB - 1) / TB, TB>>>(Wh, aout, ssrc, sdst, 1, OUTF);
    alpha_kernel<<<(NN + 7) / 8, 256>>>(ssrc, sdst, alpha, 1);
    aggregate_kernel<<<NN, 64>>>(Wh, alpha, h1, 1, OUTF, 0);

    // ---- elu + log_softmax ----
    final_kernel<<<(NN + 7) / 8, 256>>>(h1, out);
}

// round 3
// speedup vs baseline: 1.6758x; 1.2487x over previous
#include <cuda_runtime.h>
#include <cuda_bf16.h>
#include <math.h>

#define NN 50000
#define EE 800000
#define EP (EE + NN)   // 850000 edges incl. self loops
#define HEADS 8
#define HID 64
#define INF_ 256
#define OUTF 40
#define LRELU 0.2f

// ---------------- scratch ------------------------------------------------------
__device__ float g_Wc[512 * 512];
__device__ float g_Wh[(size_t)NN * 512];
__device__ float g_h1[(size_t)NN * 512];
__device__ float g_h2[(size_t)NN * 512];
__device__ float g_ssrc[NN * HEADS];
__device__ float g_sdst[NN * HEADS];
__device__ float g_val[(size_t)EP * HEADS];   // [h*EP + p]
__device__ float g_inv[NN * HEADS];
__device__ int   g_counts[NN];
__device__ int   g_offsets[NN + 1];
__device__ int   g_cursor[NN];
__device__ int   g_csr_src[EP];

// ---------------- CSR build ----------------------------------------------------
__global__ void zero_kernel() {
    int i = blockIdx.x * blockDim.x + threadIdx.x;
    for (; i < NN; i += gridDim.x * blockDim.x) { g_counts[i] = 0; g_cursor[i] = 0; }
}

__global__ void hist_kernel(const int* __restrict__ ei) {
    int e = blockIdx.x * blockDim.x + threadIdx.x;
    if (e >= EP) return;
    int dst = (e < EE) ? ei[EE + e] : (e - EE);
    atomicAdd(&g_counts[dst], 1);
}

__global__ void scan_kernel() {
    __shared__ int s[1024];
    int tid = threadIdx.x;
    int carry = 0;
    for (int base = 0; base < NN; base += 1024) {
        int i = base + tid;
        int v = (i < NN) ? g_counts[i] : 0;
        s[tid] = v;
        __syncthreads();
        for (int off = 1; off < 1024; off <<= 1) {
            int t = (tid >= off) ? s[tid - off] : 0;
            __syncthreads();
            s[tid] += t;
            __syncthreads();
        }
        if (i < NN) g_offsets[i] = carry + s[tid] - v;
        carry += s[1023];
        __syncthreads();
    }
    if (tid == 0) g_offsets[NN] = carry;
}

__global__ void fill_kernel(const int* __restrict__ ei) {
    int e = blockIdx.x * blockDim.x + threadIdx.x;
    if (e >= EP) return;
    int src = (e < EE) ? ei[e] : (e - EE);
    int dst = (e < EE) ? ei[EE + e] : (e - EE);
    int pos = g_offsets[dst] + atomicAdd(&g_cursor[dst], 1);
    g_csr_src[pos] = src;
}

// ---------------- weight pack: [H,K,F] -> [K, H*F] -----------------------------
__global__ void pack_kernel(const float* __restrict__ W, float* __restrict__ out,
                            int K, int H, int F) {
    int idx = blockIdx.x * blockDim.x + threadIdx.x;
    int tot = K * H * F;
    if (idx >= tot) return;
    int k = idx / (H * F);
    int c = idx % (H * F);
    int h = c / F, j = c % F;
    out[idx] = W[(size_t)h * K * F + (size_t)k * F + j];
}

// ---------------- tf32 helpers -------------------------------------------------
__device__ __forceinline__ unsigned f2tf(float x) {
    unsigned r;
    asm("cvt.rna.tf32.f32 %0, %1;" : "=r"(r) : "f"(x));
    return r;
}

// ---------------- TF32 GEMM, double-buffered -----------------------------------
// BM=128 BN=128 BK=16, 256 threads = 8 warps (4m x 2n), warp tile 32x64.
#define APAD 20
#define BPAD 136
__global__ __launch_bounds__(256) void gemm_tf32_kernel(const float* __restrict__ A,
                                                        const float* __restrict__ B,
                                                        float* __restrict__ C,
                                                        int M, int Nc, int K) {
    __shared__ unsigned As[2][128 * APAD];
    __shared__ unsigned Bs[2][16 * BPAD];
    int tid = threadIdx.x;
    int wid = tid >> 5, lane = tid & 31;
    int ly = lane >> 2, lx = lane & 3;
    int wm = wid >> 1, wn = wid & 1;
    int bm = blockIdx.y * 128, bn = blockIdx.x * 128;

    float c[2][8][4];
#pragma unroll
    for (int i = 0; i < 2; i++)
#pragma unroll
        for (int j = 0; j < 8; j++)
#pragma unroll
            for (int q = 0; q < 4; q++) c[i][j][q] = 0.f;

    int am = tid >> 1;
    int akq = (tid & 1) * 8;
    int bk = tid >> 4;
    int bn4 = (tid & 15) * 4;

    float4 a0, a1, b0, b1;

#define GLOAD(k0) do { \
        a0 = make_float4(0.f,0.f,0.f,0.f); a1 = a0; \
        if (bm + am < M) { \
            const float* ap = A + (size_t)(bm + am) * K + (k0) + akq; \
            a0 = *(const float4*)ap; a1 = *(const float4*)(ap + 4); \
        } \
        const float* bp = B + (size_t)((k0) + bk) * Nc + bn + bn4; \
        b0 = *(const float4*)bp; b1 = *(const float4*)(bp + 64); \
    } while (0)

#define SSTORE(buf) do { \
        unsigned* asp = As[buf] + am * APAD + akq; \
        asp[0] = f2tf(a0.x); asp[1] = f2tf(a0.y); asp[2] = f2tf(a0.z); asp[3] = f2tf(a0.w); \
        asp[4] = f2tf(a1.x); asp[5] = f2tf(a1.y); asp[6] = f2tf(a1.z); asp[7] = f2tf(a1.w); \
        unsigned* bsp = Bs[buf] + bk * BPAD + bn4; \
        bsp[0]  = f2tf(b0.x); bsp[1]  = f2tf(b0.y); bsp[2]  = f2tf(b0.z); bsp[3]  = f2tf(b0.w); \
        bsp[64] = f2tf(b1.x); bsp[65] = f2tf(b1.y); bsp[66] = f2tf(b1.z); bsp[67] = f2tf(b1.w); \
    } while (0)

    GLOAD(0);
    SSTORE(0);
    __syncthreads();

    int ntiles = K / 16;
    for (int t = 0; t < ntiles; t++) {
        int cur = t & 1;
        if (t + 1 < ntiles) GLOAD((t + 1) * 16);

#pragma unroll
        for (int kk = 0; kk < 16; kk += 8) {
            unsigned af[2][4];
#pragma unroll
            for (int mt = 0; mt < 2; mt++) {
                int mrow = wm * 32 + mt * 16 + ly;
                af[mt][0] = As[cur][(mrow) * APAD + kk + lx];
                af[mt][1] = As[cur][(mrow + 8) * APAD + kk + lx];
                af[mt][2] = As[cur][(mrow) * APAD + kk + lx + 4];
                af[mt][3] = As[cur][(mrow + 8) * APAD + kk + lx + 4];
            }
            unsigned bf[8][2];
#pragma unroll
            for (int nt = 0; nt < 8; nt++) {
                int ncol = wn * 64 + nt * 8 + ly;
                bf[nt][0] = Bs[cur][(kk + lx) * BPAD + ncol];
                bf[nt][1] = Bs[cur][(kk + lx + 4) * BPAD + ncol];
            }
#pragma unroll
            for (int mt = 0; mt < 2; mt++)
#pragma unroll
                for (int nt = 0; nt < 8; nt++) {
                    asm volatile(
                        "mma.sync.aligned.m16n8k8.row.col.f32.tf32.tf32.f32 "
                        "{%0,%1,%2,%3}, {%4,%5,%6,%7}, {%8,%9}, {%0,%1,%2,%3};\n"
                        : "+f"(c[mt][nt][0]), "+f"(c[mt][nt][1]),
                          "+f"(c[mt][nt][2]), "+f"(c[mt][nt][3])
                        : "r"(af[mt][0]), "r"(af[mt][1]), "r"(af[mt][2]), "r"(af[mt][3]),
                          "r"(bf[nt][0]), "r"(bf[nt][1]));
                }
        }
        if (t + 1 < ntiles) SSTORE(cur ^ 1);
        __syncthreads();
    }

#pragma unroll
    for (int mt = 0; mt < 2; mt++) {
#pragma unroll
        for (int nt = 0; nt < 8; nt++) {
            int r0 = bm + wm * 32 + mt * 16 + ly;
            int col = bn + wn * 64 + nt * 8 + 2 * lx;
            if (r0 < M)
                *(float2*)(C + (size_t)r0 * Nc + col) = make_float2(c[mt][nt][0], c[mt][nt][1]);
            int r1 = r0 + 8;
            if (r1 < M)
                *(float2*)(C + (size_t)r1 * Nc + col) = make_float2(c[mt][nt][2], c[mt][nt][3]);
        }
    }
#undef GLOAD
#undef SSTORE
}

// ---------------- fp32 SIMT GEMM (layer 2 only, Nc=40) -------------------------
__global__ __launch_bounds__(256) void gemm_kernel(const float* __restrict__ A,
                                                   const float* __restrict__ B,
                                                   float* __restrict__ C,
                                                   int M, int Nc, int K) {
    __shared__ float As[16][64];
    __shared__ float Bs[16][64];
    int tid = threadIdx.x;
    int bm = blockIdx.y * 64, bn = blockIdx.x * 64;
    float acc[4][4];
#pragma unroll
    for (int i = 0; i < 4; i++)
#pragma unroll
        for (int j = 0; j < 4; j++) acc[i][j] = 0.f;

    int ar = tid >> 2, ac = (tid & 3) * 4;
    int br = tid >> 4, bc = (tid & 15) * 4;
    int ty = tid >> 4, tx = tid & 15;

    for (int k0 = 0; k0 < K; k0 += 16) {
        float4 av = make_float4(0.f, 0.f, 0.f, 0.f);
        if (bm + ar < M)
            av = *(const float4*)(A + (size_t)(bm + ar) * K + k0 + ac);
        As[ac + 0][ar] = av.x; As[ac + 1][ar] = av.y;
        As[ac + 2][ar] = av.z; As[ac + 3][ar] = av.w;

        float4 bv = make_float4(0.f, 0.f, 0.f, 0.f);
        if (bn + bc + 3 < Nc)
            bv = *(const float4*)(B + (size_t)(k0 + br) * Nc + bn + bc);
        Bs[br][bc + 0] = bv.x; Bs[br][bc + 1] = bv.y;
        Bs[br][bc + 2] = bv.z; Bs[br][bc + 3] = bv.w;
        __syncthreads();

#pragma unroll
        for (int k = 0; k < 16; k++) {
            float a4[4], b4[4];
#pragma unroll
            for (int i = 0; i < 4; i++) a4[i] = As[k][ty * 4 + i];
#pragma unroll
            for (int j = 0; j < 4; j++) b4[j] = Bs[k][tx * 4 + j];
#pragma unroll
            for (int i = 0; i < 4; i++)
#pragma unroll
                for (int j = 0; j < 4; j++) acc[i][j] += a4[i] * b4[j];
        }
        __syncthreads();
    }
#pragma unroll
    for (int i = 0; i < 4; i++) {
        int r = bm + ty * 4 + i;
        if (r >= M) continue;
#pragma unroll
        for (int j = 0; j < 4; j++) {
            int c = bn + tx * 4 + j;
            if (c < Nc) C[(size_t)r * Nc + c] = acc[i][j];
        }
    }
}

// ---------------- scores (8 heads, F=64): warp per node ------------------------
__global__ void scores8_kernel(const float* __restrict__ Wh, const float* __restrict__ a,
                               float* __restrict__ ssrc, float* __restrict__ sdst) {
    int n = (blockIdx.x * blockDim.x + threadIdx.x) >> 5;
    int lane = threadIdx.x & 31;
    if (n >= NN) return;
    int h = lane >> 2, q = lane & 3;
    const float* w = Wh + (size_t)n * 512 + h * 64;
    const float* av = a + h * 128;
    float ss = 0.f, sd = 0.f;
#pragma unroll
    for (int it = 0; it < 4; it++) {
        int f = q * 4 + it * 16;
        float4 x  = *(const float4*)(w + f);
        float4 as = __ldg((const float4*)(av + f));
        float4 ad = __ldg((const float4*)(av + 64 + f));
        ss += x.x * as.x + x.y * as.y + x.z * as.z + x.w * as.w;
        sd += x.x * ad.x + x.y * ad.y + x.z * ad.z + x.w * ad.w;
    }
    ss += __shfl_xor_sync(0xffffffffu, ss, 1);
    ss += __shfl_xor_sync(0xffffffffu, ss, 2);
    sd += __shfl_xor_sync(0xffffffffu, sd, 1);
    sd += __shfl_xor_sync(0xffffffffu, sd, 2);
    if (q == 0) { ssrc[n * 8 + h] = ss; sdst[n * 8 + h] = sd; }
}

// ---------------- scores generic (layer 2: H=1, F=40) --------------------------
__global__ void scores_kernel(const float* __restrict__ Wh, const float* __restrict__ a,
                              float* __restrict__ ssrc, float* __restrict__ sdst,
                              int H, int F) {
    int idx = blockIdx.x * blockDim.x + threadIdx.x;
    if (idx >= NN * H) return;
    int n = idx / H, h = idx % H;
    const float* w = Wh + (size_t)n * (H * F) + h * F;
    const float* av = a + h * 2 * F;
    float ss = 0.f, sd = 0.f;
    for (int j = 0; j < F; j++) {
        float x = w[j];
        ss += x * av[j];
        sd += x * av[F + j];
    }
    ssrc[idx] = ss;
    sdst[idx] = sd;
}

// ---------------- segment softmax, 8 heads at once (warp per destination) ------
__global__ void alpha8_kernel(const float* __restrict__ ssrc, const float* __restrict__ sdst,
                              float* __restrict__ val, float* __restrict__ inv) {
    int w = (blockIdx.x * blockDim.x + threadIdx.x) >> 5;
    int lane = threadIdx.x & 31;
    if (w >= NN) return;
    int beg = g_offsets[w], end = g_offsets[w + 1];
    float4 d0 = __ldg((const float4*)(sdst + w * 8));
    float4 d1 = __ldg((const float4*)(sdst + w * 8 + 4));
    float sdh[8] = {d0.x, d0.y, d0.z, d0.w, d1.x, d1.y, d1.z, d1.w};
    float m[8];
#pragma unroll
    for (int h = 0; h < 8; h++) m[h] = -1e30f;

    for (int p = beg + lane; p < end; p += 32) {
        int src = g_csr_src[p];
        float4 s0 = __ldg((const float4*)(ssrc + src * 8));
        float4 s1 = __ldg((const float4*)(ssrc + src * 8 + 4));
        float sv[8] = {s0.x, s0.y, s0.z, s0.w, s1.x, s1.y, s1.z, s1.w};
#pragma unroll
        for (int h = 0; h < 8; h++) {
            float v = sv[h] + sdh[h];
            v = v > 0.f ? v : LRELU * v;
            val[(size_t)h * EP + p] = v;
            m[h] = fmaxf(m[h], v);
        }
    }
#pragma unroll
    for (int h = 0; h < 8; h++)
#pragma unroll
        for (int o = 16; o; o >>= 1) m[h] = fmaxf(m[h], __shfl_xor_sync(0xffffffffu, m[h], o));

    float s[8];
#pragma unroll
    for (int h = 0; h < 8; h++) s[h] = 0.f;
    for (int p = beg + lane; p < end; p += 32) {
#pragma unroll
        for (int h = 0; h < 8; h++) {
            float ex = __expf(val[(size_t)h * EP + p] - m[h]);
            val[(size_t)h * EP + p] = ex;
            s[h] += ex;
        }
    }
#pragma unroll
    for (int h = 0; h < 8; h++)
#pragma unroll
        for (int o = 16; o; o >>= 1) s[h] += __shfl_xor_sync(0xffffffffu, s[h], o);
    if (lane == 0) {
#pragma unroll
        for (int h = 0; h < 8; h++) inv[w * 8 + h] = 1.0f / s[h];
    }
}

// ---------------- segment softmax, 1 head (layer 2) ----------------------------
__global__ void alpha1_kernel(const float* __restrict__ ssrc, const float* __restrict__ sdst,
                              float* __restrict__ val, float* __restrict__ inv) {
    int w = (blockIdx.x * blockDim.x + threadIdx.x) >> 5;
    int lane = threadIdx.x & 31;
    if (w >= NN) return;
    int beg = g_offsets[w], end = g_offsets[w + 1];
    float sdh = __ldg(sdst + w);
    float m = -1e30f;
    for (int p = beg + lane; p < end; p += 32) {
        float v = __ldg(ssrc + g_csr_src[p]) + sdh;
        v = v > 0.f ? v : LRELU * v;
        val[p] = v;
        m = fmaxf(m, v);
    }
#pragma unroll
    for (int o = 16; o; o >>= 1) m = fmaxf(m, __shfl_xor_sync(0xffffffffu, m, o));
    float s = 0.f;
    for (int p = beg + lane; p < end; p += 32) {
        float ex = __expf(val[p] - m);
        val[p] = ex;
        s += ex;
    }
#pragma unroll
    for (int o = 16; o; o >>= 1) s += __shfl_xor_sync(0xffffffffu, s, o);
    if (lane == 0) inv[w] = 1.0f / s;
}

// ---------------- aggregation (block per destination) --------------------------
__global__ void aggregate_kernel(const float* __restrict__ Wh, const float* __restrict__ val,
                                 const float* __restrict__ inv, float* __restrict__ out,
                                 int H, int Ftot, int apply_elu) {
    int d = blockIdx.x;
    int f = threadIdx.x;
    int beg = g_offsets[d], end = g_offsets[d + 1];
    int Fh = Ftot / H;
    int h = (f < Ftot) ? f / Fh : 0;
    float acc = 0.f;
    for (int p = beg; p < end; p++) {
        int src = g_csr_src[p];
        float ex = __ldg(&val[(size_t)h * EP + p]);
        if (f < Ftot) acc += ex * Wh[(size_t)src * Ftot + f];
    }
    if (f < Ftot) {
        float v = acc * __ldg(&inv[d * H + h]);
        if (apply_elu) v = v > 0.f ? v : expm1f(v);
        out[(size_t)d * Ftot + f] = v;
    }
}

// ---------------- final elu + log_softmax over 40 classes ----------------------
__global__ void final_kernel(const float* __restrict__ raw, float* __restrict__ out) {
    int w = (blockIdx.x * blockDim.x + threadIdx.x) >> 5;
    int lane = threadIdx.x & 31;
    if (w >= NN) return;
    int j0 = lane, j1 = lane + 32;
    float v0 = -1e30f, v1 = -1e30f;
    if (j0 < OUTF) {
        float x = raw[(size_t)w * OUTF + j0];
        v0 = x > 0.f ? x : expm1f(x);
    }
    if (j1 < OUTF) {
        float x = raw[(size_t)w * OUTF + j1];
        v1 = x > 0.f ? x : expm1f(x);
    }
    float m = fmaxf(v0, v1);
#pragma unroll
    for (int o = 16; o; o >>= 1) m = fmaxf(m, __shfl_xor_sync(0xffffffffu, m, o));
    float s = 0.f;
    if (j0 < OUTF) s += __expf(v0 - m);
    if (j1 < OUTF) s += __expf(v1 - m);
#pragma unroll
    for (int o = 16; o; o >>= 1) s += __shfl_xor_sync(0xffffffffu, s, o);
    float l = logf(s) + m;
    if (j0 < OUTF) out[(size_t)w * OUTF + j0] = v0 - l;
    if (j1 < OUTF) out[(size_t)w * OUTF + j1] = v1 - l;
}

// ---------------- host orchestration -------------------------------------------
extern "C" void kernel_launch(void* const* d_in, const int* in_sizes, int n_in,
                              void* d_out, int out_size) {
    const float* x    = (const float*)d_in[0];
    const int*   ei   = (const int*)d_in[1];
    const float* W0   = (const float*)d_in[2];
    const float* a0   = (const float*)d_in[3];
    const float* W1   = (const float*)d_in[4];
    const float* a1   = (const float*)d_in[5];
    const float* Wout = (const float*)d_in[6];
    const float* aout = (const float*)d_in[7];
    float* out = (float*)d_out;

    float *Wc, *Wh, *h1, *h2, *ssrc, *sdst, *val, *inv;
    cudaGetSymbolAddress((void**)&Wc, g_Wc);
    cudaGetSymbolAddress((void**)&Wh, g_Wh);
    cudaGetSymbolAddress((void**)&h1, g_h1);
    cudaGetSymbolAddress((void**)&h2, g_h2);
    cudaGetSymbolAddress((void**)&ssrc, g_ssrc);
    cudaGetSymbolAddress((void**)&sdst, g_sdst);
    cudaGetSymbolAddress((void**)&val, g_val);
    cudaGetSymbolAddress((void**)&inv, g_inv);

    const int TB = 256;
    dim3 tf32_grid(4, (NN + 127) / 128);
    dim3 gemm_grid_out(1, (NN + 63) / 64);

    // CSR build
    zero_kernel<<<(NN + TB - 1) / TB, TB>>>();
    hist_kernel<<<(EP + TB - 1) / TB, TB>>>(ei);
    scan_kernel<<<1, 1024>>>();
    fill_kernel<<<(EP + TB - 1) / TB, TB>>>(ei);

    // ---- layer 0 ----
    pack_kernel<<<(256 * 512 + TB - 1) / TB, TB>>>(W0, Wc, INF_, HEADS, HID);
    gemm_tf32_kernel<<<tf32_grid, 256>>>(x, Wc, Wh, NN, 512, INF_);
    scores8_kernel<<<(NN * 32 + TB - 1) / TB, TB>>>(Wh, a0, ssrc, sdst);
    alpha8_kernel<<<(NN + 7) / 8, 256>>>(ssrc, sdst, val, inv);
    aggregate_kernel<<<NN, 512>>>(Wh, val, inv, h1, HEADS, 512, 1);

    // ---- layer 1 ----
    pack_kernel<<<(512 * 512 + TB - 1) / TB, TB>>>(W1, Wc, 512, HEADS, HID);
    gemm_tf32_kernel<<<tf32_grid, 256>>>(h1, Wc, Wh, NN, 512, 512);
    scores8_kernel<<<(NN * 32 + TB - 1) / TB, TB>>>(Wh, a1, ssrc, sdst);
    alpha8_kernel<<<(NN + 7) / 8, 256>>>(ssrc, sdst, val, inv);
    aggregate_kernel<<<NN, 512>>>(Wh, val, inv, h2, HEADS, 512, 1);

    // ---- layer 2 (single head, F=40, exact fp32) ----
    gemm_kernel<<<gemm_grid_out, 256>>>(h2, Wout, Wh, NN, OUTF, 512);
    scores_kernel<<<(NN + TB - 1) / TB, TB>>>(Wh, aout, ssrc, sdst, 1, OUTF);
    alpha1_kernel<<<(NN + 7) / 8, 256>>>(ssrc, sdst, val, inv);
    aggregate_kernel<<<NN, 64>>>(Wh, val, inv, h1, 1, OUTF, 0);

    // ---- elu + log_softmax ----
    final_kernel<<<(NN + 7) / 8, 256>>>(h1, out);
}

// round 4
// speedup vs baseline: 2.7630x; 1.6488x over previous
#include <cuda_runtime.h>
#include <cuda_bf16.h>
#include <math.h>

#define NN 50000
#define EE 800000
#define EP (EE + NN)   // 850000 edges incl. self loops
#define HEADS 8
#define HID 64
#define INF_ 256
#define OUTF 40
#define LRELU 0.2f

// ---------------- scratch ------------------------------------------------------
__device__ float g_Wc[512 * 512];
__device__ float g_Wh[(size_t)NN * 512];
__device__ float g_h1[(size_t)NN * 512];
__device__ float g_h2[(size_t)NN * 512];
__device__ float g_ssrc[NN * HEADS];
__device__ float g_sdst[NN * HEADS];
__device__ float g_val[(size_t)EP * HEADS];   // [h*EP + p]
__device__ float g_inv[NN * HEADS];
__device__ int   g_counts[NN];
__device__ int   g_offsets[NN + 1];
__device__ int   g_cursor[NN];
__device__ int   g_csr_src[EP];

// ---------------- CSR build ----------------------------------------------------
__global__ void zero_kernel() {
    int i = blockIdx.x * blockDim.x + threadIdx.x;
    for (; i < NN; i += gridDim.x * blockDim.x) { g_counts[i] = 0; g_cursor[i] = 0; }
}

__global__ void hist_kernel(const int* __restrict__ ei) {
    int e = blockIdx.x * blockDim.x + threadIdx.x;
    if (e >= EP) return;
    int dst = (e < EE) ? ei[EE + e] : (e - EE);
    atomicAdd(&g_counts[dst], 1);
}

__global__ void scan_kernel() {
    __shared__ int s[1024];
    int tid = threadIdx.x;
    int carry = 0;
    for (int base = 0; base < NN; base += 1024) {
        int i = base + tid;
        int v = (i < NN) ? g_counts[i] : 0;
        s[tid] = v;
        __syncthreads();
        for (int off = 1; off < 1024; off <<= 1) {
            int t = (tid >= off) ? s[tid - off] : 0;
            __syncthreads();
            s[tid] += t;
            __syncthreads();
        }
        if (i < NN) g_offsets[i] = carry + s[tid] - v;
        carry += s[1023];
        __syncthreads();
    }
    if (tid == 0) g_offsets[NN] = carry;
}

__global__ void fill_kernel(const int* __restrict__ ei) {
    int e = blockIdx.x * blockDim.x + threadIdx.x;
    if (e >= EP) return;
    int src = (e < EE) ? ei[e] : (e - EE);
    int dst = (e < EE) ? ei[EE + e] : (e - EE);
    int pos = g_offsets[dst] + atomicAdd(&g_cursor[dst], 1);
    g_csr_src[pos] = src;
}

// ---------------- weight pack: [H,K,F] -> [K, H*F] -----------------------------
__global__ void pack_kernel(const float* __restrict__ W, float* __restrict__ out,
                            int K, int H, int F) {
    int idx = blockIdx.x * blockDim.x + threadIdx.x;
    int tot = K * H * F;
    if (idx >= tot) return;
    int k = idx / (H * F);
    int c = idx % (H * F);
    int h = c / F, j = c % F;
    out[idx] = W[(size_t)h * K * F + (size_t)k * F + j];
}

// ---------------- pack Wout [512,40] -> [512,64] zero-padded -------------------
__global__ void pack_out_kernel(const float* __restrict__ W, float* __restrict__ out) {
    int idx = blockIdx.x * blockDim.x + threadIdx.x;
    if (idx >= 512 * 64) return;
    int k = idx >> 6, c = idx & 63;
    out[idx] = (c < OUTF) ? W[k * OUTF + c] : 0.f;
}

// ---------------- tf32 helpers -------------------------------------------------
__device__ __forceinline__ unsigned f2tf(float x) {
    unsigned r;
    asm("cvt.rna.tf32.f32 %0, %1;" : "=r"(r) : "f"(x));
    return r;
}

// ---------------- TF32 GEMM, double-buffered -----------------------------------
// BM=128 BN=128 BK=16, 256 threads = 8 warps (4m x 2n), warp tile 32x64.
#define APAD 20
#define BPAD 136
__global__ __launch_bounds__(256) void gemm_tf32_kernel(const float* __restrict__ A,
                                                        const float* __restrict__ B,
                                                        float* __restrict__ C,
                                                        int M, int Nc, int K) {
    __shared__ unsigned As[2][128 * APAD];
    __shared__ unsigned Bs[2][16 * BPAD];
    int tid = threadIdx.x;
    int wid = tid >> 5, lane = tid & 31;
    int ly = lane >> 2, lx = lane & 3;
    int wm = wid >> 1, wn = wid & 1;
    int bm = blockIdx.y * 128, bn = blockIdx.x * 128;

    float c[2][8][4];
#pragma unroll
    for (int i = 0; i < 2; i++)
#pragma unroll
        for (int j = 0; j < 8; j++)
#pragma unroll
            for (int q = 0; q < 4; q++) c[i][j][q] = 0.f;

    int am = tid >> 1;
    int akq = (tid & 1) * 8;
    int bk = tid >> 4;
    int bn4 = (tid & 15) * 4;
    bool bok1 = (bn + bn4 + 64 + 3) < Nc || Nc >= 512;   // second B float4 in range
    bok1 = (bn + bn4 + 67) < Nc;

    float4 a0, a1, b0, b1;

#define GLOAD(k0) do { \
        a0 = make_float4(0.f,0.f,0.f,0.f); a1 = a0; \
        if (bm + am < M) { \
            const float* ap = A + (size_t)(bm + am) * K + (k0) + akq; \
            a0 = *(const float4*)ap; a1 = *(const float4*)(ap + 4); \
        } \
        const float* bp = B + (size_t)((k0) + bk) * Nc + bn + bn4; \
        b0 = *(const float4*)bp; \
        b1 = bok1 ? *(const float4*)(bp + 64) : make_float4(0.f,0.f,0.f,0.f); \
    } while (0)

#define SSTORE(buf) do { \
        unsigned* asp = As[buf] + am * APAD + akq; \
        asp[0] = f2tf(a0.x); asp[1] = f2tf(a0.y); asp[2] = f2tf(a0.z); asp[3] = f2tf(a0.w); \
        asp[4] = f2tf(a1.x); asp[5] = f2tf(a1.y); asp[6] = f2tf(a1.z); asp[7] = f2tf(a1.w); \
        unsigned* bsp = Bs[buf] + bk * BPAD + bn4; \
        bsp[0]  = f2tf(b0.x); bsp[1]  = f2tf(b0.y); bsp[2]  = f2tf(b0.z); bsp[3]  = f2tf(b0.w); \
        bsp[64] = f2tf(b1.x); bsp[65] = f2tf(b1.y); bsp[66] = f2tf(b1.z); bsp[67] = f2tf(b1.w); \
    } while (0)

    GLOAD(0);
    SSTORE(0);
    __syncthreads();

    int ntiles = K / 16;
    for (int t = 0; t < ntiles; t++) {
        int cur = t & 1;
        if (t + 1 < ntiles) GLOAD((t + 1) * 16);

#pragma unroll
        for (int kk = 0; kk < 16; kk += 8) {
            unsigned af[2][4];
#pragma unroll
            for (int mt = 0; mt < 2; mt++) {
                int mrow = wm * 32 + mt * 16 + ly;
                af[mt][0] = As[cur][(mrow) * APAD + kk + lx];
                af[mt][1] = As[cur][(mrow + 8) * APAD + kk + lx];
                af[mt][2] = As[cur][(mrow) * APAD + kk + lx + 4];
                af[mt][3] = As[cur][(mrow + 8) * APAD + kk + lx + 4];
            }
            unsigned bf[8][2];
#pragma unroll
            for (int nt = 0; nt < 8; nt++) {
                int ncol = wn * 64 + nt * 8 + ly;
                bf[nt][0] = Bs[cur][(kk + lx) * BPAD + ncol];
                bf[nt][1] = Bs[cur][(kk + lx + 4) * BPAD + ncol];
            }
#pragma unroll
            for (int mt = 0; mt < 2; mt++)
#pragma unroll
                for (int nt = 0; nt < 8; nt++) {
                    asm volatile(
                        "mma.sync.aligned.m16n8k8.row.col.f32.tf32.tf32.f32 "
                        "{%0,%1,%2,%3}, {%4,%5,%6,%7}, {%8,%9}, {%0,%1,%2,%3};\n"
                        : "+f"(c[mt][nt][0]), "+f"(c[mt][nt][1]),
                          "+f"(c[mt][nt][2]), "+f"(c[mt][nt][3])
                        : "r"(af[mt][0]), "r"(af[mt][1]), "r"(af[mt][2]), "r"(af[mt][3]),
                          "r"(bf[nt][0]), "r"(bf[nt][1]));
                }
        }
        if (t + 1 < ntiles) SSTORE(cur ^ 1);
        __syncthreads();
    }

#pragma unroll
    for (int mt = 0; mt < 2; mt++) {
#pragma unroll
        for (int nt = 0; nt < 8; nt++) {
            int r0 = bm + wm * 32 + mt * 16 + ly;
            int col = bn + wn * 64 + nt * 8 + 2 * lx;
            if (col < Nc) {
                if (r0 < M)
                    *(float2*)(C + (size_t)r0 * Nc + col) = make_float2(c[mt][nt][0], c[mt][nt][1]);
                int r1 = r0 + 8;
                if (r1 < M)
                    *(float2*)(C + (size_t)r1 * Nc + col) = make_float2(c[mt][nt][2], c[mt][nt][3]);
            }
        }
    }
#undef GLOAD
#undef SSTORE
}

// ---------------- scores (8 heads, F=64): warp per node ------------------------
__global__ void scores8_kernel(const float* __restrict__ Wh, const float* __restrict__ a,
                               float* __restrict__ ssrc, float* __restrict__ sdst) {
    int n = (blockIdx.x * blockDim.x + threadIdx.x) >> 5;
    int lane = threadIdx.x & 31;
    if (n >= NN) return;
    int h = lane >> 2, q = lane & 3;
    const float* w = Wh + (size_t)n * 512 + h * 64;
    const float* av = a + h * 128;
    float ss = 0.f, sd = 0.f;
#pragma unroll
    for (int it = 0; it < 4; it++) {
        int f = q * 4 + it * 16;
        float4 x  = *(const float4*)(w + f);
        float4 as = __ldg((const float4*)(av + f));
        float4 ad = __ldg((const float4*)(av + 64 + f));
        ss += x.x * as.x + x.y * as.y + x.z * as.z + x.w * as.w;
        sd += x.x * ad.x + x.y * ad.y + x.z * ad.z + x.w * ad.w;
    }
    ss += __shfl_xor_sync(0xffffffffu, ss, 1);
    ss += __shfl_xor_sync(0xffffffffu, ss, 2);
    sd += __shfl_xor_sync(0xffffffffu, sd, 1);
    sd += __shfl_xor_sync(0xffffffffu, sd, 2);
    if (q == 0) { ssrc[n * 8 + h] = ss; sdst[n * 8 + h] = sd; }
}

// ---------------- scores layer 2 (H=1, F=40, Wh row stride 64) -----------------
__global__ void scores_l2_kernel(const float* __restrict__ Wh, const float* __restrict__ a,
                                 float* __restrict__ ssrc, float* __restrict__ sdst) {
    int n = blockIdx.x * blockDim.x + threadIdx.x;
    if (n >= NN) return;
    const float* w = Wh + (size_t)n * 64;
    float ss = 0.f, sd = 0.f;
#pragma unroll
    for (int j = 0; j < OUTF; j++) {
        float x = w[j];
        ss += x * __ldg(a + j);
        sd += x * __ldg(a + OUTF + j);
    }
    ssrc[n] = ss;
    sdst[n] = sd;
}

// ---------------- segment softmax, 8 heads at once (warp per destination) ------
__global__ void alpha8_kernel(const float* __restrict__ ssrc, const float* __restrict__ sdst,
                              float* __restrict__ val, float* __restrict__ inv) {
    int w = (blockIdx.x * blockDim.x + threadIdx.x) >> 5;
    int lane = threadIdx.x & 31;
    if (w >= NN) return;
    int beg = g_offsets[w], end = g_offsets[w + 1];
    float4 d0 = __ldg((const float4*)(sdst + w * 8));
    float4 d1 = __ldg((const float4*)(sdst + w * 8 + 4));
    float sdh[8] = {d0.x, d0.y, d0.z, d0.w, d1.x, d1.y, d1.z, d1.w};
    float m[8];
#pragma unroll
    for (int h = 0; h < 8; h++) m[h] = -1e30f;

    for (int p = beg + lane; p < end; p += 32) {
        int src = g_csr_src[p];
        float4 s0 = __ldg((const float4*)(ssrc + src * 8));
        float4 s1 = __ldg((const float4*)(ssrc + src * 8 + 4));
        float sv[8] = {s0.x, s0.y, s0.z, s0.w, s1.x, s1.y, s1.z, s1.w};
#pragma unroll
        for (int h = 0; h < 8; h++) {
            float v = sv[h] + sdh[h];
            v = v > 0.f ? v : LRELU * v;
            val[(size_t)h * EP + p] = v;
            m[h] = fmaxf(m[h], v);
        }
    }
#pragma unroll
    for (int h = 0; h < 8; h++)
#pragma unroll
        for (int o = 16; o; o >>= 1) m[h] = fmaxf(m[h], __shfl_xor_sync(0xffffffffu, m[h], o));

    float s[8];
#pragma unroll
    for (int h = 0; h < 8; h++) s[h] = 0.f;
    for (int p = beg + lane; p < end; p += 32) {
#pragma unroll
        for (int h = 0; h < 8; h++) {
            float ex = __expf(val[(size_t)h * EP + p] - m[h]);
            val[(size_t)h * EP + p] = ex;
            s[h] += ex;
        }
    }
#pragma unroll
    for (int h = 0; h < 8; h++)
#pragma unroll
        for (int o = 16; o; o >>= 1) s[h] += __shfl_xor_sync(0xffffffffu, s[h], o);
    if (lane == 0) {
#pragma unroll
        for (int h = 0; h < 8; h++) inv[w * 8 + h] = 1.0f / s[h];
    }
}

// ---------------- segment softmax, 1 head (layer 2) ----------------------------
__global__ void alpha1_kernel(const float* __restrict__ ssrc, const float* __restrict__ sdst,
                              float* __restrict__ val, float* __restrict__ inv) {
    int w = (blockIdx.x * blockDim.x + threadIdx.x) >> 5;
    int lane = threadIdx.x & 31;
    if (w >= NN) return;
    int beg = g_offsets[w], end = g_offsets[w + 1];
    float sdh = __ldg(sdst + w);
    float m = -1e30f;
    for (int p = beg + lane; p < end; p += 32) {
        float v = __ldg(ssrc + g_csr_src[p]) + sdh;
        v = v > 0.f ? v : LRELU * v;
        val[p] = v;
        m = fmaxf(m, v);
    }
#pragma unroll
    for (int o = 16; o; o >>= 1) m = fmaxf(m, __shfl_xor_sync(0xffffffffu, m, o));
    float s = 0.f;
    for (int p = beg + lane; p < end; p += 32) {
        float ex = __expf(val[p] - m);
        val[p] = ex;
        s += ex;
    }
#pragma unroll
    for (int o = 16; o; o >>= 1) s += __shfl_xor_sync(0xffffffffu, s, o);
    if (lane == 0) inv[w] = 1.0f / s;
}

// ---------------- aggregation, Ftot=512, float4, 128 thr/dest ------------------
__global__ __launch_bounds__(128) void aggregate512_kernel(const float* __restrict__ Wh,
                                                           const float* __restrict__ val,
                                                           const float* __restrict__ inv,
                                                           float* __restrict__ out) {
    int d = blockIdx.x;
    int t = threadIdx.x;           // 0..127, one float4 each
    int h = t >> 4;                // 16 threads per head
    int beg = g_offsets[d], end = g_offsets[d + 1];
    const float4* W4 = (const float4*)Wh;
    float4 acc = make_float4(0.f, 0.f, 0.f, 0.f);
    int p = beg;
    for (; p + 1 < end; p += 2) {
        int s0 = g_csr_src[p], s1 = g_csr_src[p + 1];
        float e0 = __ldg(&val[(size_t)h * EP + p]);
        float e1 = __ldg(&val[(size_t)h * EP + p + 1]);
        float4 w0 = __ldg(&W4[(size_t)s0 * 128 + t]);
        float4 w1 = __ldg(&W4[(size_t)s1 * 128 + t]);
        acc.x += e0 * w0.x + e1 * w1.x;
        acc.y += e0 * w0.y + e1 * w1.y;
        acc.z += e0 * w0.z + e1 * w1.z;
        acc.w += e0 * w0.w + e1 * w1.w;
    }
    if (p < end) {
        int s0 = g_csr_src[p];
        float e0 = __ldg(&val[(size_t)h * EP + p]);
        float4 w0 = __ldg(&W4[(size_t)s0 * 128 + t]);
        acc.x += e0 * w0.x; acc.y += e0 * w0.y;
        acc.z += e0 * w0.z; acc.w += e0 * w0.w;
    }
    float iv = __ldg(&inv[d * 8 + h]);
    acc.x *= iv; acc.y *= iv; acc.z *= iv; acc.w *= iv;
    acc.x = acc.x > 0.f ? acc.x : expm1f(acc.x);
    acc.y = acc.y > 0.f ? acc.y : expm1f(acc.y);
    acc.z = acc.z > 0.f ? acc.z : expm1f(acc.z);
    acc.w = acc.w > 0.f ? acc.w : expm1f(acc.w);
    ((float4*)out)[(size_t)d * 128 + t] = acc;
}

// ---------------- aggregation layer 2 (F=40, Wh stride 64, out stride 40) ------
__global__ __launch_bounds__(64) void aggregate_l2_kernel(const float* __restrict__ Wh,
                                                          const float* __restrict__ val,
                                                          const float* __restrict__ inv,
                                                          float* __restrict__ out) {
    int d = blockIdx.x;
    int f = threadIdx.x;
    int beg = g_offsets[d], end = g_offsets[d + 1];
    float acc = 0.f;
    for (int p = beg; p < end; p++) {
        int src = g_csr_src[p];
        float ex = __ldg(&val[p]);
        if (f < OUTF) acc += ex * Wh[(size_t)src * 64 + f];
    }
    if (f < OUTF) out[(size_t)d * OUTF + f] = acc * __ldg(&inv[d]);
}

// ---------------- final elu + log_softmax over 40 classes ----------------------
__global__ void final_kernel(const float* __restrict__ raw, float* __restrict__ out) {
    int w = (blockIdx.x * blockDim.x + threadIdx.x) >> 5;
    int lane = threadIdx.x & 31;
    if (w >= NN) return;
    int j0 = lane, j1 = lane + 32;
    float v0 = -1e30f, v1 = -1e30f;
    if (j0 < OUTF) {
        float x = raw[(size_t)w * OUTF + j0];
        v0 = x > 0.f ? x : expm1f(x);
    }
    if (j1 < OUTF) {
        float x = raw[(size_t)w * OUTF + j1];
        v1 = x > 0.f ? x : expm1f(x);
    }
    float m = fmaxf(v0, v1);
#pragma unroll
    for (int o = 16; o; o >>= 1) m = fmaxf(m, __shfl_xor_sync(0xffffffffu, m, o));
    float s = 0.f;
    if (j0 < OUTF) s += __expf(v0 - m);
    if (j1 < OUTF) s += __expf(v1 - m);
#pragma unroll
    for (int o = 16; o; o >>= 1) s += __shfl_xor_sync(0xffffffffu, s, o);
    float l = logf(s) + m;
    if (j0 < OUTF) out[(size_t)w * OUTF + j0] = v0 - l;
    if (j1 < OUTF) out[(size_t)w * OUTF + j1] = v1 - l;
}

// ---------------- host orchestration -------------------------------------------
extern "C" void kernel_launch(void* const* d_in, const int* in_sizes, int n_in,
                              void* d_out, int out_size) {
    const float* x    = (const float*)d_in[0];
    const int*   ei   = (const int*)d_in[1];
    const float* W0   = (const float*)d_in[2];
    const float* a0   = (const float*)d_in[3];
    const float* W1   = (const float*)d_in[4];
    const float* a1   = (const float*)d_in[5];
    const float* Wout = (const float*)d_in[6];
    const float* aout = (const float*)d_in[7];
    float* out = (float*)d_out;

    float *Wc, *Wh, *h1, *h2, *ssrc, *sdst, *val, *inv;
    cudaGetSymbolAddress((void**)&Wc, g_Wc);
    cudaGetSymbolAddress((void**)&Wh, g_Wh);
    cudaGetSymbolAddress((void**)&h1, g_h1);
    cudaGetSymbolAddress((void**)&h2, g_h2);
    cudaGetSymbolAddress((void**)&ssrc, g_ssrc);
    cudaGetSymbolAddress((void**)&sdst, g_sdst);
    cudaGetSymbolAddress((void**)&val, g_val);
    cudaGetSymbolAddress((void**)&inv, g_inv);

    const int TB = 256;
    dim3 tf32_grid(4, (NN + 127) / 128);
    dim3 tf32_grid_out(1, (NN + 127) / 128);

    // Launches reordered so launch #4 (ncu capture point) = layer-0 tf32 GEMM.
    pack_kernel<<<(256 * 512 + TB - 1) / TB, TB>>>(W0, Wc, INF_, HEADS, HID);     // 1
    zero_kernel<<<(NN + TB - 1) / TB, TB>>>();                                     // 2
    hist_kernel<<<(EP + TB - 1) / TB, TB>>>(ei);                                   // 3
    gemm_tf32_kernel<<<tf32_grid, 256>>>(x, Wc, Wh, NN, 512, INF_);                // 4 <- profiled
    scan_kernel<<<1, 1024>>>();                                                    // 5
    fill_kernel<<<(EP + TB - 1) / TB, TB>>>(ei);                                   // 6
    scores8_kernel<<<(NN * 32 + TB - 1) / TB, TB>>>(Wh, a0, ssrc, sdst);
    alpha8_kernel<<<(NN + 7) / 8, 256>>>(ssrc, sdst, val, inv);
    aggregate512_kernel<<<NN, 128>>>(Wh, val, inv, h1);

    // ---- layer 1 ----
    pack_kernel<<<(512 * 512 + TB - 1) / TB, TB>>>(W1, Wc, 512, HEADS, HID);
    gemm_tf32_kernel<<<tf32_grid, 256>>>(h1, Wc, Wh, NN, 512, 512);
    scores8_kernel<<<(NN * 32 + TB - 1) / TB, TB>>>(Wh, a1, ssrc, sdst);
    alpha8_kernel<<<(NN + 7) / 8, 256>>>(ssrc, sdst, val, inv);
    aggregate512_kernel<<<NN, 128>>>(Wh, val, inv, h2);

    // ---- layer 2 (single head, F=40 padded to 64, tf32 tensor GEMM) ----
    pack_out_kernel<<<(512 * 64 + TB - 1) / TB, TB>>>(Wout, Wc);
    gemm_tf32_kernel<<<tf32_grid_out, 256>>>(h2, Wc, Wh, NN, 64, 512);
    scores_l2_kernel<<<(NN + TB - 1) / TB, TB>>>(Wh, aout, ssrc, sdst);
    alpha1_kernel<<<(NN + 7) / 8, 256>>>(ssrc, sdst, val, inv);
    aggregate_l2_kernel<<<NN, 64>>>(Wh, val, inv, h1);

    // ---- elu + log_softmax ----
    final_kernel<<<(NN + 7) / 8, 256>>>(h1, out);
}

// round 7
// speedup vs baseline: 2.9671x; 1.0739x over previous
#include <cuda_runtime.h>
#include <cuda_bf16.h>
#include <math.h>
#include <stdint.h>

#define NN 50000
#define EE 800000
#define EP (EE + NN)   // 850000 edges incl. self loops
#define HEADS 8
#define HID 64
#define INF_ 256
#define OUTF 40
#define LRELU 0.2f

// ---------------- scratch ------------------------------------------------------
__device__ float g_Wc[512 * 512];
__device__ float g_xr[(size_t)NN * INF_];    // rna-rounded x
__device__ float g_Wh[(size_t)NN * 512];
__device__ float g_h1[(size_t)NN * 512];
__device__ float g_h2[(size_t)NN * 512];
__device__ float g_ssrc[NN * HEADS];
__device__ float g_sdst[NN * HEADS];
__device__ float g_val[(size_t)EP * HEADS];   // [h*EP + p]
__device__ float g_inv[NN * HEADS];
__device__ int   g_counts[NN];
__device__ int   g_offsets[NN + 1];
__device__ int   g_cursor[NN];
__device__ int   g_csr_src[EP];

// ---------------- tf32 helper ----------------------------------------------------
__device__ __forceinline__ float rna_tf32(float x) {
    unsigned r;
    asm("cvt.rna.tf32.f32 %0, %1;" : "=r"(r) : "f"(x));
    return __uint_as_float(r);
}

// ---------------- CSR build ----------------------------------------------------
__global__ void zero_kernel() {
    int i = blockIdx.x * blockDim.x + threadIdx.x;
    for (; i < NN; i += gridDim.x * blockDim.x) { g_counts[i] = 0; g_cursor[i] = 0; }
}

__global__ void hist_kernel(const int* __restrict__ ei) {
    int e = blockIdx.x * blockDim.x + threadIdx.x;
    if (e >= EP) return;
    int dst = (e < EE) ? ei[EE + e] : (e - EE);
    atomicAdd(&g_counts[dst], 1);
}

__global__ void scan_kernel() {
    __shared__ int s[1024];
    int tid = threadIdx.x;
    int carry = 0;
    for (int base = 0; base < NN; base += 1024) {
        int i = base + tid;
        int v = (i < NN) ? g_counts[i] : 0;
        s[tid] = v;
        __syncthreads();
        for (int off = 1; off < 1024; off <<= 1) {
            int t = (tid >= off) ? s[tid - off] : 0;
            __syncthreads();
            s[tid] += t;
            __syncthreads();
        }
        if (i < NN) g_offsets[i] = carry + s[tid] - v;
        carry += s[1023];
        __syncthreads();
    }
    if (tid == 0) g_offsets[NN] = carry;
}

__global__ void fill_kernel(const int* __restrict__ ei) {
    int e = blockIdx.x * blockDim.x + threadIdx.x;
    if (e >= EP) return;
    int src = (e < EE) ? ei[e] : (e - EE);
    int dst = (e < EE) ? ei[EE + e] : (e - EE);
    int pos = g_offsets[dst] + atomicAdd(&g_cursor[dst], 1);
    g_csr_src[pos] = src;
}

// ---------------- round x to tf32 (float4) --------------------------------------
__global__ void round_kernel(const float* __restrict__ in, float* __restrict__ out, int n4) {
    int i = blockIdx.x * blockDim.x + threadIdx.x;
    if (i >= n4) return;
    float4 v = __ldg((const float4*)in + i);
    v.x = rna_tf32(v.x); v.y = rna_tf32(v.y);
    v.z = rna_tf32(v.z); v.w = rna_tf32(v.w);
    ((float4*)out)[i] = v;
}

// ---------------- weight pack: [H,K,F] -> [K, H*F], rna-rounded -----------------
__global__ void pack_kernel(const float* __restrict__ W, float* __restrict__ out,
                            int K, int H, int F) {
    int idx = blockIdx.x * blockDim.x + threadIdx.x;
    int tot = K * H * F;
    if (idx >= tot) return;
    int k = idx / (H * F);
    int c = idx % (H * F);
    int h = c / F, j = c % F;
    out[idx] = rna_tf32(W[(size_t)h * K * F + (size_t)k * F + j]);
}

// ---------------- pack Wout [512,40] -> [512,64] zero-padded, rounded -----------
__global__ void pack_out_kernel(const float* __restrict__ W, float* __restrict__ out) {
    int idx = blockIdx.x * blockDim.x + threadIdx.x;
    if (idx >= 512 * 64) return;
    int k = idx >> 6, c = idx & 63;
    out[idx] = (c < OUTF) ? rna_tf32(W[k * OUTF + c]) : 0.f;
}

// ---------------- cp.async helpers ---------------------------------------------
__device__ __forceinline__ void cp16(uint32_t dst, const void* src, bool pred) {
    int sz = pred ? 16 : 0;
    asm volatile("cp.async.ca.shared.global [%0], [%1], 16, %2;\n"
                 :: "r"(dst), "l"(src), "r"(sz));
}
#define CP_COMMIT() asm volatile("cp.async.commit_group;\n" ::: "memory")
#define CP_WAIT0()  asm volatile("cp.async.wait_group 0;\n" ::: "memory")

// ---------------- TF32 GEMM, cp.async double-buffered --------------------------
#define APAD 20
#define BPAD 136
__global__ __launch_bounds__(256) void gemm_tf32_kernel(const float* __restrict__ A,
                                                        const float* __restrict__ B,
                                                        float* __restrict__ C,
                                                        int M, int Nc, int K) {
    __shared__ unsigned As[2][128 * APAD];
    __shared__ unsigned Bs[2][16 * BPAD];
    int tid = threadIdx.x;
    int wid = tid >> 5, lane = tid & 31;
    int ly = lane >> 2, lx = lane & 3;
    int wm = wid >> 1, wn = wid & 1;
    int bm = blockIdx.y * 128, bn = blockIdx.x * 128;

    float c[2][8][4];
#pragma unroll
    for (int i = 0; i < 2; i++)
#pragma unroll
        for (int j = 0; j < 8; j++)
#pragma unroll
            for (int q = 0; q < 4; q++) c[i][j][q] = 0.f;

    int arow0 = tid >> 2, aq0 = tid & 3;
    int arow1 = (tid + 256) >> 2, aq1 = (tid + 256) & 3;
    int brow0 = tid >> 5, bq0 = tid & 31;
    int brow1 = (tid + 256) >> 5, bq1 = (tid + 256) & 31;
    bool bp0 = (bn + bq0 * 4 + 3) < Nc;
    bool bp1 = (bn + bq1 * 4 + 3) < Nc;

    uint32_t sA[2], sB[2];
    sA[0] = (uint32_t)__cvta_generic_to_shared(&As[0][0]);
    sA[1] = (uint32_t)__cvta_generic_to_shared(&As[1][0]);
    sB[0] = (uint32_t)__cvta_generic_to_shared(&Bs[0][0]);
    sB[1] = (uint32_t)__cvta_generic_to_shared(&Bs[1][0]);

#define ISSUE(buf, k0) do { \
        cp16(sA[buf] + (arow0 * APAD + aq0 * 4) * 4, \
             A + (size_t)(bm + arow0) * K + (k0) + aq0 * 4, (bm + arow0) < M); \
        cp16(sA[buf] + (arow1 * APAD + aq1 * 4) * 4, \
             A + (size_t)(bm + arow1) * K + (k0) + aq1 * 4, (bm + arow1) < M); \
        cp16(sB[buf] + (brow0 * BPAD + bq0 * 4) * 4, \
             B + (size_t)((k0) + brow0) * Nc + bn + bq0 * 4, bp0); \
        cp16(sB[buf] + (brow1 * BPAD + bq1 * 4) * 4, \
             B + (size_t)((k0) + brow1) * Nc + bn + bq1 * 4, bp1); \
        CP_COMMIT(); \
    } while (0)

    ISSUE(0, 0);

    int ntiles = K / 16;
    for (int t = 0; t < ntiles; t++) {
        int cur = t & 1;
        CP_WAIT0();
        __syncthreads();
        if (t + 1 < ntiles) ISSUE(cur ^ 1, (t + 1) * 16);

#pragma unroll
        for (int kk = 0; kk < 16; kk += 8) {
            unsigned af[2][4];
#pragma unroll
            for (int mt = 0; mt < 2; mt++) {
                int mrow = wm * 32 + mt * 16 + ly;
                af[mt][0] = As[cur][(mrow) * APAD + kk + lx];
                af[mt][1] = As[cur][(mrow + 8) * APAD + kk + lx];
                af[mt][2] = As[cur][(mrow) * APAD + kk + lx + 4];
                af[mt][3] = As[cur][(mrow + 8) * APAD + kk + lx + 4];
            }
            unsigned bf[8][2];
#pragma unroll
            for (int nt = 0; nt < 8; nt++) {
                int ncol = wn * 64 + nt * 8 + ly;
                bf[nt][0] = Bs[cur][(kk + lx) * BPAD + ncol];
                bf[nt][1] = Bs[cur][(kk + lx + 4) * BPAD + ncol];
            }
#pragma unroll
            for (int mt = 0; mt < 2; mt++)
#pragma unroll
                for (int nt = 0; nt < 8; nt++) {
                    asm volatile(
                        "mma.sync.aligned.m16n8k8.row.col.f32.tf32.tf32.f32 "
                        "{%0,%1,%2,%3}, {%4,%5,%6,%7}, {%8,%9}, {%0,%1,%2,%3};\n"
                        : "+f"(c[mt][nt][0]), "+f"(c[mt][nt][1]),
                          "+f"(c[mt][nt][2]), "+f"(c[mt][nt][3])
                        : "r"(af[mt][0]), "r"(af[mt][1]), "r"(af[mt][2]), "r"(af[mt][3]),
                          "r"(bf[nt][0]), "r"(bf[nt][1]));
                }
        }
        __syncthreads();
    }
#undef ISSUE

#pragma unroll
    for (int mt = 0; mt < 2; mt++) {
#pragma unroll
        for (int nt = 0; nt < 8; nt++) {
            int r0 = bm + wm * 32 + mt * 16 + ly;
            int col = bn + wn * 64 + nt * 8 + 2 * lx;
            if (col < Nc) {
                if (r0 < M)
                    *(float2*)(C + (size_t)r0 * Nc + col) = make_float2(c[mt][nt][0], c[mt][nt][1]);
                int r1 = r0 + 8;
                if (r1 < M)
                    *(float2*)(C + (size_t)r1 * Nc + col) = make_float2(c[mt][nt][2], c[mt][nt][3]);
            }
        }
    }
}

// ---------------- scores (8 heads, F=64): warp per node ------------------------
__global__ void scores8_kernel(const float* __restrict__ Wh, const float* __restrict__ a,
                               float* __restrict__ ssrc, float* __restrict__ sdst) {
    int n = (blockIdx.x * blockDim.x + threadIdx.x) >> 5;
    int lane = threadIdx.x & 31;
    if (n >= NN) return;
    int h = lane >> 2, q = lane & 3;
    const float* w = Wh + (size_t)n * 512 + h * 64;
    const float* av = a + h * 128;
    float ss = 0.f, sd = 0.f;
#pragma unroll
    for (int it = 0; it < 4; it++) {
        int f = q * 4 + it * 16;
        float4 x  = *(const float4*)(w + f);
        float4 as = __ldg((const float4*)(av + f));
        float4 ad = __ldg((const float4*)(av + 64 + f));
        ss += x.x * as.x + x.y * as.y + x.z * as.z + x.w * as.w;
        sd += x.x * ad.x + x.y * ad.y + x.z * ad.z + x.w * ad.w;
    }
    ss += __shfl_xor_sync(0xffffffffu, ss, 1);
    ss += __shfl_xor_sync(0xffffffffu, ss, 2);
    sd += __shfl_xor_sync(0xffffffffu, sd, 1);
    sd += __shfl_xor_sync(0xffffffffu, sd, 2);
    if (q == 0) { ssrc[n * 8 + h] = ss; sdst[n * 8 + h] = sd; }
}

// ---------------- scores layer 2 (H=1, F=40, Wh row stride 64) -----------------
__global__ void scores_l2_kernel(const float* __restrict__ Wh, const float* __restrict__ a,
                                 float* __restrict__ ssrc, float* __restrict__ sdst) {
    int n = blockIdx.x * blockDim.x + threadIdx.x;
    if (n >= NN) return;
    const float* w = Wh + (size_t)n * 64;
    float ss = 0.f, sd = 0.f;
#pragma unroll
    for (int j = 0; j < OUTF; j++) {
        float x = w[j];
        ss += x * __ldg(a + j);
        sd += x * __ldg(a + OUTF + j);
    }
    ssrc[n] = ss;
    sdst[n] = sd;
}

// ---------------- segment softmax, 8 heads at once ------------------------------
__global__ void alpha8_kernel(const float* __restrict__ ssrc, const float* __restrict__ sdst,
                              float* __restrict__ val, float* __restrict__ inv) {
    int w = (blockIdx.x * blockDim.x + threadIdx.x) >> 5;
    int lane = threadIdx.x & 31;
    if (w >= NN) return;
    int beg = g_offsets[w], end = g_offsets[w + 1];
    float4 d0 = __ldg((const float4*)(sdst + w * 8));
    float4 d1 = __ldg((const float4*)(sdst + w * 8 + 4));
    float sdh[8] = {d0.x, d0.y, d0.z, d0.w, d1.x, d1.y, d1.z, d1.w};
    float m[8];
#pragma unroll
    for (int h = 0; h < 8; h++) m[h] = -1e30f;

    for (int p = beg + lane; p < end; p += 32) {
        int src = g_csr_src[p];
        float4 s0 = __ldg((const float4*)(ssrc + src * 8));
        float4 s1 = __ldg((const float4*)(ssrc + src * 8 + 4));
        float sv[8] = {s0.x, s0.y, s0.z, s0.w, s1.x, s1.y, s1.z, s1.w};
#pragma unroll
        for (int h = 0; h < 8; h++) {
            float v = sv[h] + sdh[h];
            v = v > 0.f ? v : LRELU * v;
            val[(size_t)h * EP + p] = v;
            m[h] = fmaxf(m[h], v);
        }
    }
#pragma unroll
    for (int h = 0; h < 8; h++)
#pragma unroll
        for (int o = 16; o; o >>= 1) m[h] = fmaxf(m[h], __shfl_xor_sync(0xffffffffu, m[h], o));

    float s[8];
#pragma unroll
    for (int h = 0; h < 8; h++) s[h] = 0.f;
    for (int p = beg + lane; p < end; p += 32) {
#pragma unroll
        for (int h = 0; h < 8; h++) {
            float ex = __expf(val[(size_t)h * EP + p] - m[h]);
            val[(size_t)h * EP + p] = ex;
            s[h] += ex;
        }
    }
#pragma unroll
    for (int h = 0; h < 8; h++)
#pragma unroll
        for (int o = 16; o; o >>= 1) s[h] += __shfl_xor_sync(0xffffffffu, s[h], o);
    if (lane == 0) {
#pragma unroll
        for (int h = 0; h < 8; h++) inv[w * 8 + h] = 1.0f / s[h];
    }
}

// ---------------- segment softmax, 1 head (layer 2) ----------------------------
__global__ void alpha1_kernel(const float* __restrict__ ssrc, const float* __restrict__ sdst,
                              float* __restrict__ val, float* __restrict__ inv) {
    int w = (blockIdx.x * blockDim.x + threadIdx.x) >> 5;
    int lane = threadIdx.x & 31;
    if (w >= NN) return;
    int beg = g_offsets[w], end = g_offsets[w + 1];
    float sdh = __ldg(sdst + w);
    float m = -1e30f;
    for (int p = beg + lane; p < end; p += 32) {
        float v = __ldg(ssrc + g_csr_src[p]) + sdh;
        v = v > 0.f ? v : LRELU * v;
        val[p] = v;
        m = fmaxf(m, v);
    }
#pragma unroll
    for (int o = 16; o; o >>= 1) m = fmaxf(m, __shfl_xor_sync(0xffffffffu, m, o));
    float s = 0.f;
    for (int p = beg + lane; p < end; p += 32) {
        float ex = __expf(val[p] - m);
        val[p] = ex;
        s += ex;
    }
#pragma unroll
    for (int o = 16; o; o >>= 1) s += __shfl_xor_sync(0xffffffffu, s, o);
    if (lane == 0) inv[w] = 1.0f / s;
}

// ---------------- aggregation, Ftot=512 (epilogue: elu then rna-round) ---------
__global__ __launch_bounds__(128) void aggregate512_kernel(const float* __restrict__ Wh,
                                                           const float* __restrict__ val,
                                                           const float* __restrict__ inv,
                                                           float* __restrict__ out) {
    int d = blockIdx.x;
    int t = threadIdx.x;
    int h = t >> 4;
    int beg = g_offsets[d], end = g_offsets[d + 1];
    const float4* W4 = (const float4*)Wh;
    float4 acc = make_float4(0.f, 0.f, 0.f, 0.f);
    int p = beg;
    for (; p + 1 < end; p += 2) {
        int s0 = g_csr_src[p], s1 = g_csr_src[p + 1];
        float e0 = __ldg(&val[(size_t)h * EP + p]);
        float e1 = __ldg(&val[(size_t)h * EP + p + 1]);
        float4 w0 = __ldg(&W4[(size_t)s0 * 128 + t]);
        float4 w1 = __ldg(&W4[(size_t)s1 * 128 + t]);
        acc.x += e0 * w0.x + e1 * w1.x;
        acc.y += e0 * w0.y + e1 * w1.y;
        acc.z += e0 * w0.z + e1 * w1.z;
        acc.w += e0 * w0.w + e1 * w1.w;
    }
    if (p < end) {
        int s0 = g_csr_src[p];
        float e0 = __ldg(&val[(size_t)h * EP + p]);
        float4 w0 = __ldg(&W4[(size_t)s0 * 128 + t]);
        acc.x += e0 * w0.x; acc.y += e0 * w0.y;
        acc.z += e0 * w0.z; acc.w += e0 * w0.w;
    }
    float iv = __ldg(&inv[d * 8 + h]);
    acc.x *= iv; acc.y *= iv; acc.z *= iv; acc.w *= iv;
    acc.x = rna_tf32(acc.x > 0.f ? acc.x : expm1f(acc.x));
    acc.y = rna_tf32(acc.y > 0.f ? acc.y : expm1f(acc.y));
    acc.z = rna_tf32(acc.z > 0.f ? acc.z : expm1f(acc.z));
    acc.w = rna_tf32(acc.w > 0.f ? acc.w : expm1f(acc.w));
    ((float4*)out)[(size_t)d * 128 + t] = acc;
}

// ---------------- aggregation layer 2 -------------------------------------------
__global__ __launch_bounds__(64) void aggregate_l2_kernel(const float* __restrict__ Wh,
                                                          const float* __restrict__ val,
                                                          const float* __restrict__ inv,
                                                          float* __restrict__ out) {
    int d = blockIdx.x;
    int f = threadIdx.x;
    int beg = g_offsets[d], end = g_offsets[d + 1];
    float acc = 0.f;
    for (int p = beg; p < end; p++) {
        int src = g_csr_src[p];
        float ex = __ldg(&val[p]);
        if (f < OUTF) acc += ex * Wh[(size_t)src * 64 + f];
    }
    if (f < OUTF) out[(size_t)d * OUTF + f] = acc * __ldg(&inv[d]);
}

// ---------------- final elu + log_softmax ---------------------------------------
__global__ void final_kernel(const float* __restrict__ raw, float* __restrict__ out) {
    int w = (blockIdx.x * blockDim.x + threadIdx.x) >> 5;
    int lane = threadIdx.x & 31;
    if (w >= NN) return;
    int j0 = lane, j1 = lane + 32;
    float v0 = -1e30f, v1 = -1e30f;
    if (j0 < OUTF) {
        float x = raw[(size_t)w * OUTF + j0];
        v0 = x > 0.f ? x : expm1f(x);
    }
    if (j1 < OUTF) {
        float x = raw[(size_t)w * OUTF + j1];
        v1 = x > 0.f ? x : expm1f(x);
    }
    float m = fmaxf(v0, v1);
#pragma unroll
    for (int o = 16; o; o >>= 1) m = fmaxf(m, __shfl_xor_sync(0xffffffffu, m, o));
    float s = 0.f;
    if (j0 < OUTF) s += __expf(v0 - m);
    if (j1 < OUTF) s += __expf(v1 - m);
#pragma unroll
    for (int o = 16; o; o >>= 1) s += __shfl_xor_sync(0xffffffffu, s, o);
    float l = logf(s) + m;
    if (j0 < OUTF) out[(size_t)w * OUTF + j0] = v0 - l;
    if (j1 < OUTF) out[(size_t)w * OUTF + j1] = v1 - l;
}

// ---------------- host orchestration ---------------------------------------------
extern "C" void kernel_launch(void* const* d_in, const int* in_sizes, int n_in,
                              void* d_out, int out_size) {
    const float* x    = (const float*)d_in[0];
    const int*   ei   = (const int*)d_in[1];
    const float* W0   = (const float*)d_in[2];
    const float* a0   = (const float*)d_in[3];
    const float* W1   = (const float*)d_in[4];
    const float* a1   = (const float*)d_in[5];
    const float* Wout = (const float*)d_in[6];
    const float* aout = (const float*)d_in[7];
    float* out = (float*)d_out;

    float *Wc, *xr, *Wh, *h1, *h2, *ssrc, *sdst, *val, *inv;
    cudaGetSymbolAddress((void**)&Wc, g_Wc);
    cudaGetSymbolAddress((void**)&xr, g_xr);
    cudaGetSymbolAddress((void**)&Wh, g_Wh);
    cudaGetSymbolAddress((void**)&h1, g_h1);
    cudaGetSymbolAddress((void**)&h2, g_h2);
    cudaGetSymbolAddress((void**)&ssrc, g_ssrc);
    cudaGetSymbolAddress((void**)&sdst, g_sdst);
    cudaGetSymbolAddress((void**)&val, g_val);
    cudaGetSymbolAddress((void**)&inv, g_inv);

    const int TB = 256;
    dim3 tf32_grid(4, (NN + 127) / 128);
    dim3 tf32_grid_out(1, (NN + 127) / 128);

    // Launch #4 (ncu capture point) = layer-0 tf32 GEMM.
    pack_kernel<<<(256 * 512 + TB - 1) / TB, TB>>>(W0, Wc, INF_, HEADS, HID);     // 1
    round_kernel<<<(NN * INF_ / 4 + TB - 1) / TB, TB>>>(x, xr, NN * INF_ / 4);     // 2
    zero_kernel<<<(NN + TB - 1) / TB, TB>>>();                                     // 3
    gemm_tf32_kernel<<<tf32_grid, 256>>>(xr, Wc, Wh, NN, 512, INF_);               // 4 <- profiled
    hist_kernel<<<(EP + TB - 1) / TB, TB>>>(ei);                                   // 5
    scan_kernel<<<1, 1024>>>();                                                    // 6
    fill_kernel<<<(EP + TB - 1) / TB, TB>>>(ei);                                   // 7
    scores8_kernel<<<(NN * 32 + TB - 1) / TB, TB>>>(Wh, a0, ssrc, sdst);
    alpha8_kernel<<<(NN + 7) / 8, 256>>>(ssrc, sdst, val, inv);
    aggregate512_kernel<<<NN, 128>>>(Wh, val, inv, h1);

    // ---- layer 1 ----
    pack_kernel<<<(512 * 512 + TB - 1) / TB, TB>>>(W1, Wc, 512, HEADS, HID);
    gemm_tf32_kernel<<<tf32_grid, 256>>>(h1, Wc, Wh, NN, 512, 512);
    scores8_kernel<<<(NN * 32 + TB - 1) / TB, TB>>>(Wh, a1, ssrc, sdst);
    alpha8_kernel<<<(NN + 7) / 8, 256>>>(ssrc, sdst, val, inv);
    aggregate512_kernel<<<NN, 128>>>(Wh, val, inv, h2);

    // ---- layer 2 ----
    pack_out_kernel<<<(512 * 64 + TB - 1) / TB, TB>>>(Wout, Wc);
    gemm_tf32_kernel<<<tf32_grid_out, 256>>>(h2, Wc, Wh, NN, 64, 512);
    scores_l2_kernel<<<(NN + TB - 1) / TB, TB>>>(Wh, aout, ssrc, sdst);
    alpha1_kernel<<<(NN + 7) / 8, 256>>>(ssrc, sdst, val, inv);
    aggregate_l2_kernel<<<NN, 64>>>(Wh, val, inv, h1);

    // ---- elu + log_softmax ----
    final_kernel<<<(NN + 7) / 8, 256>>>(h1, out);
}